// round 3
// baseline (speedup 1.0000x reference)
#include <cuda_runtime.h>
#include <cuda_bf16.h>
#include <math.h>

// ---------------- constants ----------------
// B=16, N=1024, T=12, F=1, D_MODEL=512, D_K=D_V=32, H=3, K=3, C=32

// ---------------- scratch (static device memory; no allocation) ----------------
__device__ float g_TEmx[16 * 12 * 1024];      // (B,T,N)
__device__ float g_ctx [16 * 12 * 96];        // (B,T,96)
__device__ float g_TAT [16 * 12 * 1024];      // (B,T,N)
__device__ float g_SEmx[16 * 1024 * 512];     // (B,N,512)
__device__ float g_QKs [16 * 1024 * 192];     // (B,N,192): cols 0..95 = Qs, 96..191 = Ks
__device__ float g_rhs [16 * 3 * 1024 * 12];  // (B,K,N,T)
__device__ float g_Wr  [32 * 15 * 64];        // reordered gtu weights [ci][pos][oc2]

// ---------------- helpers ----------------
__device__ __forceinline__ void block_reduce2(float& s, float& s2, float* shm) {
    // blockDim.x == 256
    #pragma unroll
    for (int o = 16; o > 0; o >>= 1) {
        s  += __shfl_down_sync(0xFFFFFFFFu, s,  o);
        s2 += __shfl_down_sync(0xFFFFFFFFu, s2, o);
    }
    int w = threadIdx.x >> 5, l = threadIdx.x & 31;
    if (l == 0) { shm[w] = s; shm[w + 32] = s2; }
    __syncthreads();
    if (w == 0) {
        s  = (l < 8) ? shm[l] : 0.f;
        s2 = (l < 8) ? shm[l + 32] : 0.f;
        #pragma unroll
        for (int o = 4; o > 0; o >>= 1) {
            s  += __shfl_down_sync(0xFFFFFFFFu, s,  o);
            s2 += __shfl_down_sync(0xFFFFFFFFu, s2, o);
        }
        if (l == 0) { shm[0] = s; shm[1] = s2; }
    }
    __syncthreads();
    s = shm[0]; s2 = shm[1];
}

// ---------------- K1: temporal embed + LN over N ----------------
__global__ void k_temporal_ln(const float* __restrict__ x, const float* __restrict__ peT,
                              const float* __restrict__ gT, const float* __restrict__ bT) {
    int b = blockIdx.x / 12, t = blockIdx.x % 12;
    int tid = threadIdx.x;
    __shared__ float shm[64];
    float vals[4]; float s = 0.f, s2 = 0.f;
    #pragma unroll
    for (int i = 0; i < 4; i++) {
        int n = tid + 256 * i;
        float v = x[((size_t)b * 1024 + n) * 12 + t] + peT[t * 1024 + n];
        vals[i] = v; s += v; s2 += v * v;
    }
    block_reduce2(s, s2, shm);
    float mu = s * (1.f / 1024.f);
    float rstd = rsqrtf(s2 * (1.f / 1024.f) - mu * mu + 1e-5f);
    float* op = g_TEmx + ((size_t)b * 12 + t) * 1024;
    #pragma unroll
    for (int i = 0; i < 4; i++) {
        int n = tid + 256 * i;
        op[n] = (vals[i] - mu) * rstd * gT[n] + bT[n];
    }
}

// ---------------- K2a: temporal MHA per (b,h); writes re_At to out tail ----------------
__global__ void k_temporal_attn(const float* __restrict__ WQ, const float* __restrict__ WK,
                                const float* __restrict__ WV, const float* __restrict__ resa,
                                float* __restrict__ reat) {
    int b = blockIdx.x / 3, h = blockIdx.x % 3;
    int tid = threadIdx.x;
    int t = tid >> 5, d = tid & 31;         // 384 threads = 12 warps x 32
    __shared__ float Q[12][32], Kt[12][32], V[12][32], S[12][12];

    const float* E = g_TEmx + (size_t)b * 12288 + (size_t)t * 1024;
    int col = h * 32 + d;
    float q = 0.f, k = 0.f, v = 0.f;
    for (int n = 0; n < 1024; n++) {
        float e = E[n];
        q += e * WQ[n * 96 + col];
        k += e * WK[n * 96 + col];
        v += e * WV[n * 96 + col];
    }
    Q[t][d] = q; Kt[t][d] = k; V[t][d] = v;
    __syncthreads();

    if (tid < 144) {
        int qi = tid / 12, ki = tid % 12;
        float s = 0.f;
        #pragma unroll
        for (int dd = 0; dd < 32; dd++) s += Q[qi][dd] * Kt[ki][dd];
        s = s * 0.17677669529663687f + resa[((size_t)(b * 3 + h) * 12 + qi) * 12 + ki];
        S[qi][ki] = s;
        reat[((size_t)(b * 3 + h) * 12 + qi) * 12 + ki] = s;
    }
    __syncthreads();
    if (tid < 12) {
        float mxv = -1e30f;
        for (int kx = 0; kx < 12; kx++) mxv = fmaxf(mxv, S[tid][kx]);
        float smv = 0.f;
        for (int kx = 0; kx < 12; kx++) { float pv = __expf(S[tid][kx] - mxv); S[tid][kx] = pv; smv += pv; }
        float inv = 1.f / smv;
        for (int kx = 0; kx < 12; kx++) S[tid][kx] *= inv;
    }
    __syncthreads();
    float cv = 0.f;
    #pragma unroll
    for (int kx = 0; kx < 12; kx++) cv += S[t][kx] * V[kx][d];
    g_ctx[((size_t)b * 12 + t) * 96 + col] = cv;
}

// ---------------- K2b: TATout = LN(ctx @ fc_t + TEmx), gamma=1 beta=0 ----------------
__global__ void k_tatout(const float* __restrict__ fct) {
    int b = blockIdx.x / 12, t = blockIdx.x % 12;
    int tid = threadIdx.x;
    __shared__ float cs[96];
    __shared__ float shm[64];
    if (tid < 96) cs[tid] = g_ctx[((size_t)b * 12 + t) * 96 + tid];
    __syncthreads();
    const float* Eb = g_TEmx + ((size_t)b * 12 + t) * 1024;
    float vals[4]; float s = 0.f, s2 = 0.f;
    #pragma unroll
    for (int i = 0; i < 4; i++) {
        int n = tid + 256 * i;
        float v = Eb[n];
        for (int jx = 0; jx < 96; jx++) v += cs[jx] * fct[jx * 1024 + n];
        vals[i] = v; s += v; s2 += v * v;
    }
    block_reduce2(s, s2, shm);
    float mu = s * (1.f / 1024.f);
    float rstd = rsqrtf(s2 * (1.f / 1024.f) - mu * mu + 1e-5f);
    float* Tb = g_TAT + ((size_t)b * 12 + t) * 1024;
    #pragma unroll
    for (int i = 0; i < 4; i++) {
        int n = tid + 256 * i;
        Tb[n] = (vals[i] - mu) * rstd;
    }
}

// ---------------- K3a: pre_conv + pos_embed_S + LN over 512 -> SEmx ----------------
__global__ void k_semx(const float* __restrict__ pcw, const float* __restrict__ pcb,
                       const float* __restrict__ peS, const float* __restrict__ gS,
                       const float* __restrict__ bS) {
    int bx = blockIdx.x; int b = bx >> 10; int n = bx & 1023;
    int tid = threadIdx.x;
    __shared__ float tat[12];
    __shared__ float shm[64];
    if (tid < 12) tat[tid] = g_TAT[((size_t)b * 12 + tid) * 1024 + n];
    __syncthreads();
    float vals[2]; float s = 0.f, s2 = 0.f;
    #pragma unroll
    for (int i = 0; i < 2; i++) {
        int dd = tid + 256 * i;
        float v = pcb[dd] + peS[(size_t)n * 512 + dd];
        #pragma unroll
        for (int t = 0; t < 12; t++) v += tat[t] * __ldg(&pcw[dd * 12 + t]);
        vals[i] = v; s += v; s2 += v * v;
    }
    block_reduce2(s, s2, shm);
    float mu = s * (1.f / 512.f);
    float rstd = rsqrtf(s2 * (1.f / 512.f) - mu * mu + 1e-5f);
    float* op = g_SEmx + ((size_t)b * 1024 + n) * 512;
    #pragma unroll
    for (int i = 0; i < 2; i++) {
        int dd = tid + 256 * i;
        op[dd] = (vals[i] - mu) * rstd * gS[dd] + bS[dd];
    }
}

// ---------------- K3b: GEMM QKs = SEmx(16384x512) @ [WQ_s|WK_s](512x192) ----------------
__global__ void k_qks_gemm(const float* __restrict__ WQ, const float* __restrict__ WK) {
    __shared__ float As[8][128];
    __shared__ float Bs[8][64];
    int m0 = blockIdx.x * 128;
    int jb = blockIdx.y * 64;
    int tid = threadIdx.x;
    int tx = tid % 16, ty = tid / 16;
    float acc[8][4];
    #pragma unroll
    for (int r = 0; r < 8; r++)
        #pragma unroll
        for (int cq = 0; cq < 4; cq++) acc[r][cq] = 0.f;

    for (int k0 = 0; k0 < 512; k0 += 8) {
        {
            int m = tid >> 1; int kq = (tid & 1) * 4;
            float4 a = *(const float4*)&g_SEmx[((size_t)m0 + m) * 512 + k0 + kq];
            As[kq + 0][m] = a.x; As[kq + 1][m] = a.y; As[kq + 2][m] = a.z; As[kq + 3][m] = a.w;
        }
        #pragma unroll
        for (int i = 0; i < 2; i++) {
            int e = tid + 256 * i; int kk = e >> 6; int j = e & 63; int jg = jb + j;
            Bs[kk][j] = (jg < 96) ? WQ[(k0 + kk) * 96 + jg] : WK[(k0 + kk) * 96 + (jg - 96)];
        }
        __syncthreads();
        #pragma unroll
        for (int kk = 0; kk < 8; kk++) {
            float a[8], bv[4];
            #pragma unroll
            for (int r = 0; r < 8; r++) a[r] = As[kk][ty * 8 + r];
            #pragma unroll
            for (int cq = 0; cq < 4; cq++) bv[cq] = Bs[kk][tx * 4 + cq];
            #pragma unroll
            for (int r = 0; r < 8; r++)
                #pragma unroll
                for (int cq = 0; cq < 4; cq++) acc[r][cq] += a[r] * bv[cq];
        }
        __syncthreads();
    }
    #pragma unroll
    for (int r = 0; r < 8; r++)
        #pragma unroll
        for (int cq = 0; cq < 4; cq++)
            g_QKs[((size_t)m0 + ty * 8 + r) * 192 + jb + tx * 4 + cq] = acc[r][cq];
}

// ---------------- K4: spatial column-softmax flash attention ----------------
// For output column j: score[m] = Qs[b,k,m,:].Ks[b,k,j,:]/sqrt(32) + adj[m,j]*mask[k,m,j]
// rhs[b,k,j,t] = sum_m softmax_m(score)[m] * cheb[k,m,j] * x[b,m,t]
__global__ void k_spatial(const float* __restrict__ x, const float* __restrict__ adj,
                          const float* __restrict__ cmask, const float* __restrict__ cheb) {
    int j0 = blockIdx.x * 32; int kk = blockIdx.y; int b = blockIdx.z;
    int tid = threadIdx.x; int lane = tid & 31; int g = tid >> 5;
    int j = j0 + lane;

    float kreg[32];
    const float* kb = g_QKs + ((size_t)b * 1024 + j) * 192 + 96 + kk * 32;
    #pragma unroll
    for (int d = 0; d < 32; d++) kreg[d] = kb[d];

    float mx = -1e30f, sm = 0.f, acc[12];
    #pragma unroll
    for (int t = 0; t < 12; t++) acc[t] = 0.f;

    __shared__ float Qs_s[32][32];
    __shared__ float xs[32][12];

    const size_t kbase = (size_t)kk * 1048576;

    for (int it = 0; it < 32; it++) {
        int m0 = it * 32;
        #pragma unroll
        for (int i = 0; i < 4; i++) {
            int e = tid + 256 * i; int m = e >> 5; int d = e & 31;
            Qs_s[m][d] = g_QKs[((size_t)b * 1024 + m0 + m) * 192 + kk * 32 + d];
        }
        if (tid < 192) {
            #pragma unroll
            for (int i = 0; i < 2; i++) {
                int e = tid + 192 * i; int m = e / 12; int t = e % 12;
                xs[m][t] = x[((size_t)b * 1024 + m0 + m) * 12 + t];
            }
        }
        __syncthreads();
        #pragma unroll
        for (int mi = 0; mi < 4; mi++) {
            int m = g * 4 + mi;
            float s = 0.f;
            #pragma unroll
            for (int d = 0; d < 32; d++) s += Qs_s[m][d] * kreg[d];
            size_t gidx = (size_t)(m0 + m) * 1024 + j;
            float bias = adj[gidx] * cmask[kbase + gidx];
            float cp = cheb[kbase + gidx];
            s = s * 0.17677669529663687f + bias;
            float nm = fmaxf(mx, s);
            float corr = __expf(mx - nm);
            float p = __expf(s - nm);
            sm = sm * corr + p;
            float w = p * cp;
            #pragma unroll
            for (int t = 0; t < 12; t++) acc[t] = acc[t] * corr + w * xs[m][t];
            mx = nm;
        }
        __syncthreads();
    }

    // merge 8 warp-partials per j
    __shared__ float r_mx[8][32], r_sm[8][32], r_acc[8][32][12];
    r_mx[g][lane] = mx; r_sm[g][lane] = sm;
    #pragma unroll
    for (int t = 0; t < 12; t++) r_acc[g][lane][t] = acc[t];
    __syncthreads();
    if (g == 0) {
        float M = -1e30f;
        #pragma unroll
        for (int q = 0; q < 8; q++) M = fmaxf(M, r_mx[q][lane]);
        float S = 0.f; float o[12];
        #pragma unroll
        for (int t = 0; t < 12; t++) o[t] = 0.f;
        #pragma unroll
        for (int q = 0; q < 8; q++) {
            float e = __expf(r_mx[q][lane] - M);
            S += r_sm[q][lane] * e;
            #pragma unroll
            for (int t = 0; t < 12; t++) o[t] += r_acc[q][lane][t] * e;
        }
        float inv = 1.f / S;
        float* rp = g_rhs + (((size_t)b * 3 + kk) * 1024 + j) * 12;
        #pragma unroll
        for (int t = 0; t < 12; t++) rp[t] = o[t] * inv;
    }
}

// ---------------- K5: reorder gtu weights to [ci][pos][oc2] ----------------
__global__ void k_wreorder(const float* __restrict__ w3, const float* __restrict__ w5,
                           const float* __restrict__ w7) {
    int idx = blockIdx.x * 256 + threadIdx.x;
    if (idx >= 30720) return;
    int oc2 = idx & 63; int rest = idx >> 6; int pos = rest % 15; int ci = rest / 15;
    float v;
    if (pos < 3)      v = w3[(oc2 * 32 + ci) * 3 + pos];
    else if (pos < 8) v = w5[(oc2 * 32 + ci) * 5 + (pos - 3)];
    else              v = w7[(oc2 * 32 + ci) * 7 + (pos - 8)];
    g_Wr[(ci * 15 + pos) * 64 + oc2] = v;
}

// ---------------- K6: Theta contraction + GTUs + fcmy + residual + final LN ----------------
__global__ void __launch_bounds__(256) k_gtu(
    const float* __restrict__ x, const float* __restrict__ Theta,
    const float* __restrict__ b3, const float* __restrict__ b5, const float* __restrict__ b7,
    const float* __restrict__ rcw, const float* __restrict__ rcb,
    const float* __restrict__ fcw, const float* __restrict__ fcb,
    const float* __restrict__ gf, const float* __restrict__ bfin,
    float* __restrict__ out) {
    int n0 = blockIdx.x * 8; int b = blockIdx.y;
    int tid = threadIdx.x; int c = tid & 31; int p = tid >> 5; int n = n0 + p;
    __shared__ float Xs[8][32][12];
    __shared__ float Vs[8][32][12];

    // spatial_gcn[b,n,c,t] = relu(sum_k rhs[b,k,n,t] * Theta[k,0,c])
    {
        float th0 = Theta[c], th1 = Theta[32 + c], th2 = Theta[64 + c];
        const float* r0 = g_rhs + (((size_t)b * 3 + 0) * 1024 + n) * 12;
        const float* r1 = g_rhs + (((size_t)b * 3 + 1) * 1024 + n) * 12;
        const float* r2 = g_rhs + (((size_t)b * 3 + 2) * 1024 + n) * 12;
        #pragma unroll
        for (int t = 0; t < 12; t++) {
            float v = r0[t] * th0 + r1[t] * th1 + r2[t] * th2;
            Xs[p][c][t] = fmaxf(v, 0.f);
        }
    }
    __syncthreads();

    float ya[24], yb[24];
    {
        float a3 = b3[c], bB3 = b3[c + 32];
        float a5 = b5[c], bB5 = b5[c + 32];
        float a7 = b7[c], bB7 = b7[c + 32];
        #pragma unroll
        for (int w = 0; w < 10; w++) { ya[w] = a3; yb[w] = bB3; }
        #pragma unroll
        for (int w = 0; w < 8; w++)  { ya[10 + w] = a5; yb[10 + w] = bB5; }
        #pragma unroll
        for (int w = 0; w < 6; w++)  { ya[18 + w] = a7; yb[18 + w] = bB7; }
    }

    for (int ci = 0; ci < 32; ci++) {
        float X[12];
        #pragma unroll
        for (int t = 0; t < 12; t++) X[t] = Xs[p][ci][t];
        const float* wr = g_Wr + ci * 15 * 64;
        #pragma unroll
        for (int dt = 0; dt < 3; dt++) {
            float wa = wr[dt * 64 + c], wb = wr[dt * 64 + c + 32];
            #pragma unroll
            for (int w = 0; w < 10; w++) { ya[w] += X[w + dt] * wa; yb[w] += X[w + dt] * wb; }
        }
        #pragma unroll
        for (int dt = 0; dt < 5; dt++) {
            float wa = wr[(3 + dt) * 64 + c], wb = wr[(3 + dt) * 64 + c + 32];
            #pragma unroll
            for (int w = 0; w < 8; w++) { ya[10 + w] += X[w + dt] * wa; yb[10 + w] += X[w + dt] * wb; }
        }
        #pragma unroll
        for (int dt = 0; dt < 7; dt++) {
            float wa = wr[(8 + dt) * 64 + c], wb = wr[(8 + dt) * 64 + c + 32];
            #pragma unroll
            for (int w = 0; w < 6; w++) { ya[18 + w] += X[w + dt] * wa; yb[18 + w] += X[w + dt] * wb; }
        }
    }

    float gv[24];
    #pragma unroll
    for (int w = 0; w < 24; w++) {
        float tv = tanhf(ya[w]);
        float sv = 1.f / (1.f + __expf(-yb[w]));
        gv[w] = tv * sv;
    }

    float rw = rcw[c], rb = rcb[c];
    const float* xp = x + ((size_t)b * 1024 + n) * 12;
    #pragma unroll
    for (int t = 0; t < 12; t++) {
        float v = fcb[t];
        #pragma unroll
        for (int w = 0; w < 24; w++) v += gv[w] * __ldg(&fcw[w * 12 + t]);
        v = fmaxf(v, 0.f);                 // tco = relu(time_conv)
        float res = xp[t] * rw + rb;       // 1x1 residual conv
        Vs[p][c][t] = fmaxf(res + v, 0.f); // relu(x_res + tco)
    }
    __syncthreads();

    // final LN over channels for each (n,t)
    if (tid < 96) {
        int p2 = tid / 12, t2 = tid % 12;
        float s = 0.f, s2 = 0.f;
        #pragma unroll
        for (int cc = 0; cc < 32; cc++) { float v = Vs[p2][cc][t2]; s += v; s2 += v * v; }
        float mu = s * (1.f / 32.f);
        float var = s2 * (1.f / 32.f) - mu * mu;
        float rstd = rsqrtf(var + 1e-5f);
        float* op = out + (((size_t)b * 1024 + n0 + p2) * 32) * 12 + t2;
        #pragma unroll
        for (int cc = 0; cc < 32; cc++)
            op[cc * 12] = (Vs[p2][cc][t2] - mu) * rstd * gf[cc] + bfin[cc];
    }
}

// ---------------- launch ----------------
extern "C" void kernel_launch(void* const* d_in, const int* in_sizes, int n_in,
                              void* d_out, int out_size) {
    const float* x     = (const float*)d_in[0];
    const float* resa  = (const float*)d_in[1];
    const float* peT   = (const float*)d_in[2];
    const float* gT    = (const float*)d_in[3];
    const float* bT    = (const float*)d_in[4];
    const float* WQt   = (const float*)d_in[5];
    const float* WKt   = (const float*)d_in[6];
    const float* WVt   = (const float*)d_in[7];
    const float* fct   = (const float*)d_in[8];
    const float* pcw   = (const float*)d_in[9];
    const float* pcb   = (const float*)d_in[10];
    const float* peS   = (const float*)d_in[11];
    const float* gS    = (const float*)d_in[12];
    const float* bS    = (const float*)d_in[13];
    const float* WQs   = (const float*)d_in[14];
    const float* WKs   = (const float*)d_in[15];
    const float* cheb  = (const float*)d_in[16];
    const float* adj   = (const float*)d_in[17];
    const float* cmask = (const float*)d_in[18];
    const float* Theta = (const float*)d_in[19];
    const float* w3    = (const float*)d_in[20];
    const float* b3    = (const float*)d_in[21];
    const float* w5    = (const float*)d_in[22];
    const float* b5    = (const float*)d_in[23];
    const float* w7    = (const float*)d_in[24];
    const float* b7    = (const float*)d_in[25];
    const float* rcw   = (const float*)d_in[26];
    const float* rcb   = (const float*)d_in[27];
    const float* fcw   = (const float*)d_in[28];
    const float* fcb   = (const float*)d_in[29];
    const float* gf    = (const float*)d_in[30];
    const float* bf    = (const float*)d_in[31];

    float* out  = (float*)d_out;
    float* reat = out + (size_t)16 * 1024 * 32 * 12;  // re_At after main output

    k_temporal_ln<<<192, 256>>>(x, peT, gT, bT);
    k_temporal_attn<<<48, 384>>>(WQt, WKt, WVt, resa, reat);
    k_tatout<<<192, 256>>>(fct);
    k_semx<<<16384, 256>>>(pcw, pcb, peS, gS, bS);
    k_qks_gemm<<<dim3(128, 3), 256>>>(WQs, WKs);
    k_wreorder<<<120, 256>>>(w3, w5, w7);
    k_spatial<<<dim3(32, 3, 16), 256>>>(x, adj, cmask, cheb);
    k_gtu<<<dim3(128, 16), 256>>>(x, Theta, b3, b5, b7, rcw, rcb, fcw, fcb, gf, bf, out);
}

// round 4
// speedup vs baseline: 1.2887x; 1.2887x over previous
#include <cuda_runtime.h>
#include <cuda_bf16.h>
#include <math.h>

// ---------------- constants ----------------
// B=16, N=1024, T=12, F=1, D_MODEL=512, D_K=D_V=32, H=3, K=3, C=32

// ---------------- scratch (static device memory; no allocation) ----------------
__device__ float g_TEmx[16 * 12 * 1024];      // (B,T,N)
__device__ float g_qkv [16 * 12 * 288];       // (B,T,288) Q|K|V
__device__ float g_ctx [16 * 12 * 96];        // (B,T,96)
__device__ float g_TAT [16 * 12 * 1024];      // (B,T,N)
__device__ float g_SEmx[16 * 1024 * 512];     // (B,N,512)
__device__ float g_QKs [16 * 1024 * 192];     // (B,N,192): 0..95 = Qs, 96..191 = Ks
__device__ float g_rhs [16 * 3 * 1024 * 12];  // (B,K,N,T)
__device__ unsigned long long g_Wr2[32 * 15 * 32];        // {wa,wb} per (ci,pos,c)
__device__ unsigned long long g_bc [3 * 1024 * 1024];     // {adj*cmask, cheb} per (k,m,j)

// ---------------- f32x2 helpers ----------------
__device__ __forceinline__ unsigned long long pk2(float a, float b) {
    unsigned long long r; asm("mov.b64 %0, {%1,%2};" : "=l"(r) : "f"(a), "f"(b)); return r;
}
__device__ __forceinline__ void unpk(unsigned long long v, float& a, float& b) {
    asm("mov.b64 {%0,%1}, %2;" : "=f"(a), "=f"(b) : "l"(v));
}
__device__ __forceinline__ unsigned long long ffma2(unsigned long long a, unsigned long long b, unsigned long long c) {
    unsigned long long d; asm("fma.rn.f32x2 %0, %1, %2, %3;" : "=l"(d) : "l"(a), "l"(b), "l"(c)); return d;
}
__device__ __forceinline__ unsigned long long mul2(unsigned long long a, unsigned long long b) {
    unsigned long long d; asm("mul.rn.f32x2 %0, %1, %2;" : "=l"(d) : "l"(a), "l"(b)); return d;
}
__device__ __forceinline__ unsigned long long add2(unsigned long long a, unsigned long long b) {
    unsigned long long d; asm("add.rn.f32x2 %0, %1, %2;" : "=l"(d) : "l"(a), "l"(b)); return d;
}

// ---------------- helpers ----------------
__device__ __forceinline__ void block_reduce2(float& s, float& s2, float* shm) {
    // blockDim.x == 256
    #pragma unroll
    for (int o = 16; o > 0; o >>= 1) {
        s  += __shfl_down_sync(0xFFFFFFFFu, s,  o);
        s2 += __shfl_down_sync(0xFFFFFFFFu, s2, o);
    }
    int w = threadIdx.x >> 5, l = threadIdx.x & 31;
    if (l == 0) { shm[w] = s; shm[w + 32] = s2; }
    __syncthreads();
    if (w == 0) {
        s  = (l < 8) ? shm[l] : 0.f;
        s2 = (l < 8) ? shm[l + 32] : 0.f;
        #pragma unroll
        for (int o = 4; o > 0; o >>= 1) {
            s  += __shfl_down_sync(0xFFFFFFFFu, s,  o);
            s2 += __shfl_down_sync(0xFFFFFFFFu, s2, o);
        }
        if (l == 0) { shm[0] = s; shm[1] = s2; }
    }
    __syncthreads();
    s = shm[0]; s2 = shm[1];
}

// ---------------- K1: temporal embed + LN over N ----------------
__global__ void k_temporal_ln(const float* __restrict__ x, const float* __restrict__ peT,
                              const float* __restrict__ gT, const float* __restrict__ bT) {
    int b = blockIdx.x / 12, t = blockIdx.x % 12;
    int tid = threadIdx.x;
    __shared__ float shm[64];
    float vals[4]; float s = 0.f, s2 = 0.f;
    #pragma unroll
    for (int i = 0; i < 4; i++) {
        int n = tid + 256 * i;
        float v = x[((size_t)b * 1024 + n) * 12 + t] + peT[t * 1024 + n];
        vals[i] = v; s += v; s2 += v * v;
    }
    block_reduce2(s, s2, shm);
    float mu = s * (1.f / 1024.f);
    float rstd = rsqrtf(s2 * (1.f / 1024.f) - mu * mu + 1e-5f);
    float* op = g_TEmx + ((size_t)b * 12 + t) * 1024;
    #pragma unroll
    for (int i = 0; i < 4; i++) {
        int n = tid + 256 * i;
        op[n] = (vals[i] - mu) * rstd * gT[n] + bT[n];
    }
}

// ---------------- K2a: QKV projection (B,T rows x 288 cols, K=1024) ----------------
__global__ void k_qkv(const float* __restrict__ WQ, const float* __restrict__ WK,
                      const float* __restrict__ WV) {
    int b = blockIdx.x / 12, t = blockIdx.x % 12;
    int tid = threadIdx.x;  // 288 threads
    __shared__ float Es[1024];
    for (int i = tid; i < 1024; i += 288) Es[i] = g_TEmx[((size_t)b * 12 + t) * 1024 + i];
    __syncthreads();
    const float* W; int cw;
    if (tid < 96)      { W = WQ; cw = tid; }
    else if (tid < 192){ W = WK; cw = tid - 96; }
    else               { W = WV; cw = tid - 192; }
    float acc = 0.f;
    #pragma unroll 8
    for (int nn = 0; nn < 1024; nn++) acc += Es[nn] * W[nn * 96 + cw];
    g_qkv[((size_t)b * 12 + t) * 288 + tid] = acc;
}

// ---------------- K2b: temporal attention per (b,h); writes re_At ----------------
__global__ void k_tattn(const float* __restrict__ resa, float* __restrict__ reat) {
    int b = blockIdx.x / 3, h = blockIdx.x % 3;
    int tid = threadIdx.x;
    int t = tid >> 5, d = tid & 31;   // 384 threads = 12 warps x 32
    __shared__ float Q[12][32], Kt[12][32], V[12][32], S[12][12];

    const float* qb = g_qkv + ((size_t)b * 12 + t) * 288;
    Q [t][d] = qb[h * 32 + d];
    Kt[t][d] = qb[96 + h * 32 + d];
    V [t][d] = qb[192 + h * 32 + d];
    __syncthreads();

    if (tid < 144) {
        int qi = tid / 12, ki = tid % 12;
        float s = 0.f;
        #pragma unroll
        for (int dd = 0; dd < 32; dd++) s += Q[qi][dd] * Kt[ki][dd];
        s = s * 0.17677669529663687f + resa[((size_t)(b * 3 + h) * 12 + qi) * 12 + ki];
        S[qi][ki] = s;
        reat[((size_t)(b * 3 + h) * 12 + qi) * 12 + ki] = s;
    }
    __syncthreads();
    if (tid < 12) {
        float mxv = -1e30f;
        for (int kx = 0; kx < 12; kx++) mxv = fmaxf(mxv, S[tid][kx]);
        float smv = 0.f;
        for (int kx = 0; kx < 12; kx++) { float pv = __expf(S[tid][kx] - mxv); S[tid][kx] = pv; smv += pv; }
        float inv = 1.f / smv;
        for (int kx = 0; kx < 12; kx++) S[tid][kx] *= inv;
    }
    __syncthreads();
    float cv = 0.f;
    #pragma unroll
    for (int kx = 0; kx < 12; kx++) cv += S[t][kx] * V[kx][d];
    g_ctx[((size_t)b * 12 + t) * 96 + h * 32 + d] = cv;
}

// ---------------- K2c: TATout = LN(ctx @ fc_t + TEmx) ----------------
__global__ void k_tatout(const float* __restrict__ fct) {
    int b = blockIdx.x / 12, t = blockIdx.x % 12;
    int tid = threadIdx.x;
    __shared__ unsigned long long csp[96];
    __shared__ float shm[64];
    if (tid < 96) { float cv = g_ctx[((size_t)b * 12 + t) * 96 + tid]; csp[tid] = pk2(cv, cv); }
    __syncthreads();
    const unsigned long long* Eb2 = (const unsigned long long*)g_TEmx + ((size_t)b * 12 + t) * 512;
    const unsigned long long* fct2 = (const unsigned long long*)fct;
    unsigned long long v2a = Eb2[tid], v2b = Eb2[tid + 256];
    for (int jx = 0; jx < 96; jx++) {
        unsigned long long cv = csp[jx];
        v2a = ffma2(cv, fct2[(size_t)jx * 512 + tid], v2a);
        v2b = ffma2(cv, fct2[(size_t)jx * 512 + tid + 256], v2b);
    }
    float va[4];
    unpk(v2a, va[0], va[1]); unpk(v2b, va[2], va[3]);
    float s = 0.f, s2 = 0.f;
    #pragma unroll
    for (int i = 0; i < 4; i++) { s += va[i]; s2 += va[i] * va[i]; }
    block_reduce2(s, s2, shm);
    float mu = s * (1.f / 1024.f);
    float rstd = rsqrtf(s2 * (1.f / 1024.f) - mu * mu + 1e-5f);
    unsigned long long* Tb2 = (unsigned long long*)g_TAT + ((size_t)b * 12 + t) * 512;
    Tb2[tid]       = pk2((va[0] - mu) * rstd, (va[1] - mu) * rstd);
    Tb2[tid + 256] = pk2((va[2] - mu) * rstd, (va[3] - mu) * rstd);
}

// ---------------- K3a: pre_conv + pos_embed_S + LN over 512 -> SEmx ----------------
__global__ void __launch_bounds__(256) k_semx(
        const float* __restrict__ pcw, const float* __restrict__ pcb,
        const float* __restrict__ peS, const float* __restrict__ gS,
        const float* __restrict__ bS) {
    int tid = threadIdx.x;
    int b = blockIdx.x >> 7;
    int n = ((blockIdx.x & 127) << 3) + (tid >> 5);
    int lane = tid & 31;
    __shared__ unsigned long long pcws[12][256];
    #pragma unroll
    for (int t = 0; t < 12; t++)
        pcws[t][tid] = pk2(pcw[(2 * tid) * 12 + t], pcw[(2 * tid + 1) * 12 + t]);
    __syncthreads();

    float tv = 0.f;
    if (lane < 12) tv = g_TAT[((size_t)b * 12 + lane) * 1024 + n];
    unsigned long long ttp[12];
    #pragma unroll
    for (int t = 0; t < 12; t++) {
        float sv = __shfl_sync(0xFFFFFFFFu, tv, t);
        ttp[t] = pk2(sv, sv);
    }
    const unsigned long long* pcb2 = (const unsigned long long*)pcb;
    const unsigned long long* peS2 = (const unsigned long long*)peS + (size_t)n * 256;
    unsigned long long v2[8];
    float s = 0.f, s2 = 0.f;
    #pragma unroll
    for (int i = 0; i < 8; i++) {
        int dp = lane + 32 * i;
        unsigned long long v = add2(pcb2[dp], peS2[dp]);
        #pragma unroll
        for (int t = 0; t < 12; t++) v = ffma2(ttp[t], pcws[t][dp], v);
        v2[i] = v;
        float a, bb; unpk(v, a, bb);
        s += a + bb; s2 += a * a + bb * bb;
    }
    #pragma unroll
    for (int o = 16; o > 0; o >>= 1) {
        s  += __shfl_xor_sync(0xFFFFFFFFu, s,  o);
        s2 += __shfl_xor_sync(0xFFFFFFFFu, s2, o);
    }
    float mu = s * (1.f / 512.f);
    float rstd = rsqrtf(s2 * (1.f / 512.f) - mu * mu + 1e-5f);
    const unsigned long long* g2  = (const unsigned long long*)gS;
    const unsigned long long* bb2 = (const unsigned long long*)bS;
    unsigned long long* o2 = (unsigned long long*)g_SEmx + ((size_t)b * 1024 + n) * 256;
    #pragma unroll
    for (int i = 0; i < 8; i++) {
        int dp = lane + 32 * i;
        float a, bbv; unpk(v2[i], a, bbv);
        float ga, gb; unpk(g2[dp], ga, gb);
        float ba, bx; unpk(bb2[dp], ba, bx);
        o2[dp] = pk2((a - mu) * rstd * ga + ba, (bbv - mu) * rstd * gb + bx);
    }
}

// ---------------- K3b: GEMM QKs = SEmx(16384x512) @ [WQ_s|WK_s](512x192) ----------------
__global__ void __launch_bounds__(256) k_qks_gemm(const float* __restrict__ WQ,
                                                  const float* __restrict__ WK) {
    __shared__ __align__(16) float As[16][128];
    __shared__ __align__(16) float Bs[16][64];
    int m0 = blockIdx.x * 128;
    int jb = blockIdx.y * 64;
    int tid = threadIdx.x;
    int tx = tid % 16, ty = tid / 16;
    unsigned long long acc2[8][2];
    #pragma unroll
    for (int r = 0; r < 8; r++) { acc2[r][0] = 0ull; acc2[r][1] = 0ull; }

    for (int k0 = 0; k0 < 512; k0 += 16) {
        #pragma unroll
        for (int i = 0; i < 2; i++) {
            int e = tid + 256 * i; int m = e >> 2; int kq = (e & 3) * 4;
            float4 a = *(const float4*)&g_SEmx[((size_t)m0 + m) * 512 + k0 + kq];
            As[kq + 0][m] = a.x; As[kq + 1][m] = a.y; As[kq + 2][m] = a.z; As[kq + 3][m] = a.w;
        }
        #pragma unroll
        for (int i = 0; i < 4; i++) {
            int e = tid + 256 * i; int kk = e >> 6; int jl = e & 63; int jg = jb + jl;
            Bs[kk][jl] = (jg < 96) ? WQ[(k0 + kk) * 96 + jg] : WK[(k0 + kk) * 96 + (jg - 96)];
        }
        __syncthreads();
        #pragma unroll
        for (int kk = 0; kk < 16; kk++) {
            float4 a0 = *(const float4*)&As[kk][ty * 8];
            float4 a1 = *(const float4*)&As[kk][ty * 8 + 4];
            unsigned long long b0 = *(const unsigned long long*)&Bs[kk][tx * 4];
            unsigned long long b1 = *(const unsigned long long*)&Bs[kk][tx * 4 + 2];
            float av[8] = {a0.x, a0.y, a0.z, a0.w, a1.x, a1.y, a1.z, a1.w};
            #pragma unroll
            for (int r = 0; r < 8; r++) {
                unsigned long long ap = pk2(av[r], av[r]);
                acc2[r][0] = ffma2(ap, b0, acc2[r][0]);
                acc2[r][1] = ffma2(ap, b1, acc2[r][1]);
            }
        }
        __syncthreads();
    }
    unsigned long long* out64 = (unsigned long long*)g_QKs;
    #pragma unroll
    for (int r = 0; r < 8; r++) {
        size_t base = ((size_t)m0 + ty * 8 + r) * 96 + (jb >> 1) + tx * 2;
        out64[base]     = acc2[r][0];
        out64[base + 1] = acc2[r][1];
    }
}

// ---------------- K3c: precompute {adj*cmask, cheb} packed ----------------
__global__ void k_bc(const float* __restrict__ adj, const float* __restrict__ cmask,
                     const float* __restrict__ cheb) {
    int idx = blockIdx.x * 256 + threadIdx.x;   // 3*1024*1024 total
    int mj = idx & 1048575;
    float bias = adj[mj] * cmask[idx];
    g_bc[idx] = pk2(bias, cheb[idx]);
}

// ---------------- K4: spatial column-softmax flash attention ----------------
__global__ void __launch_bounds__(256) k_spatial(const float* __restrict__ x) {
    int j0 = blockIdx.x * 32; int kk = blockIdx.y; int b = blockIdx.z;
    int tid = threadIdx.x; int lane = tid & 31; int g = tid >> 5;
    int j = j0 + lane;

    const unsigned long long* qk64 = (const unsigned long long*)g_QKs;

    unsigned long long kp[16];
    {
        const ulonglong2* kb = (const ulonglong2*)(qk64 + ((size_t)b * 1024 + j) * 96 + 48 + kk * 16);
        #pragma unroll
        for (int i = 0; i < 8; i++) { ulonglong2 v = kb[i]; kp[2 * i] = v.x; kp[2 * i + 1] = v.y; }
    }

    float mx = -1e30f, sm = 0.f;
    unsigned long long acc[6];
    #pragma unroll
    for (int i = 0; i < 6; i++) acc[i] = 0ull;

    __shared__ __align__(16) unsigned long long Qs64[32][16];
    __shared__ unsigned long long xs64[32][6];

    const size_t kbase = (size_t)kk << 20;

    for (int it = 0; it < 32; it++) {
        int m0 = it * 32;
        #pragma unroll
        for (int i = 0; i < 2; i++) {
            int e = tid + 256 * i; int m = e >> 4; int d8 = e & 15;
            Qs64[m][d8] = qk64[((size_t)b * 1024 + m0 + m) * 96 + kk * 16 + d8];
        }
        if (tid < 192) {
            int m = tid / 6, i2 = tid % 6;
            xs64[m][i2] = ((const unsigned long long*)x)[((size_t)b * 1024 + m0 + m) * 6 + i2];
        }
        __syncthreads();

        float sv[4], cpv[4];
        #pragma unroll
        for (int mi = 0; mi < 4; mi++) {
            int m = g * 4 + mi;
            unsigned long long s2 = 0ull;
            const ulonglong2* qrow = (const ulonglong2*)Qs64[m];
            #pragma unroll
            for (int i = 0; i < 8; i++) {
                ulonglong2 q2 = qrow[i];
                s2 = ffma2(q2.x, kp[2 * i], s2);
                s2 = ffma2(q2.y, kp[2 * i + 1], s2);
            }
            float slo, shi; unpk(s2, slo, shi);
            float bias, cp; unpk(g_bc[kbase + (size_t)(m0 + m) * 1024 + j], bias, cp);
            sv[mi] = (slo + shi) * 0.17677669529663687f + bias;
            cpv[mi] = cp;
        }
        float tmax = fmaxf(fmaxf(sv[0], sv[1]), fmaxf(sv[2], sv[3]));
        float nm = fmaxf(mx, tmax);
        float corr = __expf(mx - nm);
        sm *= corr;
        unsigned long long corrp = pk2(corr, corr);
        #pragma unroll
        for (int i = 0; i < 6; i++) acc[i] = mul2(acc[i], corrp);
        #pragma unroll
        for (int mi = 0; mi < 4; mi++) {
            int m = g * 4 + mi;
            float p = __expf(sv[mi] - nm);
            sm += p;
            float w = p * cpv[mi];
            unsigned long long wp = pk2(w, w);
            #pragma unroll
            for (int i = 0; i < 6; i++) acc[i] = ffma2(wp, xs64[m][i], acc[i]);
        }
        mx = nm;
        __syncthreads();
    }

    // merge 8 warp-partials per j
    __shared__ float r_mx[8][32], r_sm[8][32];
    __shared__ unsigned long long r_acc[8][32][6];
    r_mx[g][lane] = mx; r_sm[g][lane] = sm;
    #pragma unroll
    for (int i = 0; i < 6; i++) r_acc[g][lane][i] = acc[i];
    __syncthreads();
    if (g == 0) {
        float M = -1e30f;
        #pragma unroll
        for (int q = 0; q < 8; q++) M = fmaxf(M, r_mx[q][lane]);
        float S = 0.f;
        unsigned long long o[6];
        #pragma unroll
        for (int i = 0; i < 6; i++) o[i] = 0ull;
        #pragma unroll
        for (int q = 0; q < 8; q++) {
            float e = __expf(r_mx[q][lane] - M);
            S += r_sm[q][lane] * e;
            unsigned long long ep = pk2(e, e);
            #pragma unroll
            for (int i = 0; i < 6; i++) o[i] = ffma2(ep, r_acc[q][lane][i], o[i]);
        }
        float inv = 1.f / S;
        unsigned long long* rp = (unsigned long long*)g_rhs + (((size_t)b * 3 + kk) * 1024 + j) * 6;
        #pragma unroll
        for (int i = 0; i < 6; i++) {
            float a, bv; unpk(o[i], a, bv);
            rp[i] = pk2(a * inv, bv * inv);
        }
    }
}

// ---------------- K5: reorder gtu weights to packed {wa,wb} ----------------
__global__ void k_wreorder(const float* __restrict__ w3, const float* __restrict__ w5,
                           const float* __restrict__ w7) {
    int idx = blockIdx.x * 256 + threadIdx.x;
    if (idx >= 15360) return;
    int c = idx & 31; int rest = idx >> 5; int pos = rest % 15; int ci = rest / 15;
    float wa, wb;
    if (pos < 3)      { wa = w3[(c * 32 + ci) * 3 + pos];       wb = w3[((c + 32) * 32 + ci) * 3 + pos]; }
    else if (pos < 8) { wa = w5[(c * 32 + ci) * 5 + (pos - 3)]; wb = w5[((c + 32) * 32 + ci) * 5 + (pos - 3)]; }
    else              { wa = w7[(c * 32 + ci) * 7 + (pos - 8)]; wb = w7[((c + 32) * 32 + ci) * 7 + (pos - 8)]; }
    g_Wr2[(ci * 15 + pos) * 32 + c] = pk2(wa, wb);
}

// ---------------- K6: Theta contraction + GTUs + fcmy + residual + final LN ----------------
__global__ void __launch_bounds__(256) k_gtu(
    const float* __restrict__ x, const float* __restrict__ Theta,
    const float* __restrict__ b3, const float* __restrict__ b5, const float* __restrict__ b7,
    const float* __restrict__ rcw, const float* __restrict__ rcb,
    const float* __restrict__ fcw, const float* __restrict__ fcb,
    const float* __restrict__ gf, const float* __restrict__ bfin,
    float* __restrict__ out) {
    int n0 = blockIdx.x * 8; int b = blockIdx.y;
    int tid = threadIdx.x; int c = tid & 31; int p = tid >> 5; int n = n0 + p;
    __shared__ unsigned long long Xp[8][32][12];
    __shared__ float Vs[8][32][12];
    __shared__ unsigned long long fcw2[24][6];

    if (tid < 144) {
        int w = tid / 6, t2 = tid % 6;
        fcw2[w][t2] = pk2(fcw[w * 12 + 2 * t2], fcw[w * 12 + 2 * t2 + 1]);
    }

    // spatial_gcn[b,n,c,t] = relu(sum_k rhs[b,k,n,t] * Theta[k,0,c]) -> packed {v,v}
    {
        float th0 = Theta[c], th1 = Theta[32 + c], th2 = Theta[64 + c];
        const float* r0 = g_rhs + (((size_t)b * 3 + 0) * 1024 + n) * 12;
        const float* r1 = g_rhs + (((size_t)b * 3 + 1) * 1024 + n) * 12;
        const float* r2 = g_rhs + (((size_t)b * 3 + 2) * 1024 + n) * 12;
        #pragma unroll
        for (int t = 0; t < 12; t++) {
            float v = r0[t] * th0 + r1[t] * th1 + r2[t] * th2;
            v = fmaxf(v, 0.f);
            Xp[p][c][t] = pk2(v, v);
        }
    }
    __syncthreads();

    unsigned long long yab[24];
    {
        unsigned long long i3 = pk2(b3[c], b3[c + 32]);
        unsigned long long i5 = pk2(b5[c], b5[c + 32]);
        unsigned long long i7 = pk2(b7[c], b7[c + 32]);
        #pragma unroll
        for (int w = 0; w < 10; w++) yab[w] = i3;
        #pragma unroll
        for (int w = 0; w < 8; w++)  yab[10 + w] = i5;
        #pragma unroll
        for (int w = 0; w < 6; w++)  yab[18 + w] = i7;
    }

    for (int ci = 0; ci < 32; ci++) {
        unsigned long long Xr[12];
        #pragma unroll
        for (int t = 0; t < 12; t++) Xr[t] = Xp[p][ci][t];
        const unsigned long long* wr = g_Wr2 + (size_t)ci * 15 * 32 + c;
        #pragma unroll
        for (int dt = 0; dt < 3; dt++) {
            unsigned long long wv = wr[dt * 32];
            #pragma unroll
            for (int w = 0; w < 10; w++) yab[w] = ffma2(Xr[w + dt], wv, yab[w]);
        }
        #pragma unroll
        for (int dt = 0; dt < 5; dt++) {
            unsigned long long wv = wr[(3 + dt) * 32];
            #pragma unroll
            for (int w = 0; w < 8; w++) yab[10 + w] = ffma2(Xr[w + dt], wv, yab[10 + w]);
        }
        #pragma unroll
        for (int dt = 0; dt < 7; dt++) {
            unsigned long long wv = wr[(8 + dt) * 32];
            #pragma unroll
            for (int w = 0; w < 6; w++) yab[18 + w] = ffma2(Xr[w + dt], wv, yab[18 + w]);
        }
    }

    // gating + fcmy (packed over t-pairs)
    unsigned long long v2[6];
    {
        const unsigned long long* fcb2 = (const unsigned long long*)fcb;
        #pragma unroll
        for (int t2 = 0; t2 < 6; t2++) v2[t2] = fcb2[t2];
    }
    #pragma unroll
    for (int w = 0; w < 24; w++) {
        float ya, yb; unpk(yab[w], ya, yb);
        float tv = 1.f - 2.f / (__expf(2.f * ya) + 1.f);
        float sg = 1.f / (1.f + __expf(-yb));
        float gv = tv * sg;
        unsigned long long gp = pk2(gv, gv);
        #pragma unroll
        for (int t2 = 0; t2 < 6; t2++) v2[t2] = ffma2(gp, fcw2[w][t2], v2[t2]);
    }

    float rw = rcw[c], rb = rcb[c];
    const unsigned long long* xp2 = (const unsigned long long*)x + ((size_t)b * 1024 + n) * 6;
    #pragma unroll
    for (int t2 = 0; t2 < 6; t2++) {
        float va, vb; unpk(v2[t2], va, vb);
        float xa, xb; unpk(xp2[t2], xa, xb);
        va = fmaxf(va, 0.f); vb = fmaxf(vb, 0.f);
        Vs[p][c][2 * t2]     = fmaxf(xa * rw + rb + va, 0.f);
        Vs[p][c][2 * t2 + 1] = fmaxf(xb * rw + rb + vb, 0.f);
    }
    __syncthreads();

    // final LN over channels for each (n,t)
    if (tid < 96) {
        int p2 = tid / 12, t2 = tid % 12;
        float s = 0.f, s2 = 0.f;
        #pragma unroll
        for (int cc = 0; cc < 32; cc++) { float v = Vs[p2][cc][t2]; s += v; s2 += v * v; }
        float mu = s * (1.f / 32.f);
        float var = s2 * (1.f / 32.f) - mu * mu;
        float rstd = rsqrtf(var + 1e-5f);
        float* op = out + (((size_t)b * 1024 + n0 + p2) * 32) * 12 + t2;
        #pragma unroll
        for (int cc = 0; cc < 32; cc++)
            op[cc * 12] = (Vs[p2][cc][t2] - mu) * rstd * gf[cc] + bfin[cc];
    }
}

// ---------------- launch ----------------
extern "C" void kernel_launch(void* const* d_in, const int* in_sizes, int n_in,
                              void* d_out, int out_size) {
    const float* x     = (const float*)d_in[0];
    const float* resa  = (const float*)d_in[1];
    const float* peT   = (const float*)d_in[2];
    const float* gT    = (const float*)d_in[3];
    const float* bT    = (const float*)d_in[4];
    const float* WQt   = (const float*)d_in[5];
    const float* WKt   = (const float*)d_in[6];
    const float* WVt   = (const float*)d_in[7];
    const float* fct   = (const float*)d_in[8];
    const float* pcw   = (const float*)d_in[9];
    const float* pcb   = (const float*)d_in[10];
    const float* peS   = (const float*)d_in[11];
    const float* gS    = (const float*)d_in[12];
    const float* bS    = (const float*)d_in[13];
    const float* WQs   = (const float*)d_in[14];
    const float* WKs   = (const float*)d_in[15];
    const float* cheb  = (const float*)d_in[16];
    const float* adj   = (const float*)d_in[17];
    const float* cmask = (const float*)d_in[18];
    const float* Theta = (const float*)d_in[19];
    const float* w3    = (const float*)d_in[20];
    const float* b3    = (const float*)d_in[21];
    const float* w5    = (const float*)d_in[22];
    const float* b5    = (const float*)d_in[23];
    const float* w7    = (const float*)d_in[24];
    const float* b7    = (const float*)d_in[25];
    const float* rcw   = (const float*)d_in[26];
    const float* rcb   = (const float*)d_in[27];
    const float* fcw   = (const float*)d_in[28];
    const float* fcb   = (const float*)d_in[29];
    const float* gf    = (const float*)d_in[30];
    const float* bf    = (const float*)d_in[31];

    float* out  = (float*)d_out;
    float* reat = out + (size_t)16 * 1024 * 32 * 12;  // re_At after main output

    k_temporal_ln<<<192, 256>>>(x, peT, gT, bT);
    k_qkv<<<192, 288>>>(WQt, WKt, WVt);
    k_tattn<<<48, 384>>>(resa, reat);
    k_tatout<<<192, 256>>>(fct);
    k_semx<<<2048, 256>>>(pcw, pcb, peS, gS, bS);
    k_qks_gemm<<<dim3(128, 3), 256>>>(WQs, WKs);
    k_wreorder<<<60, 256>>>(w3, w5, w7);
    k_bc<<<12288, 256>>>(adj, cmask, cheb);
    k_spatial<<<dim3(32, 3, 16), 256>>>(x);
    k_gtu<<<dim3(128, 16), 256>>>(x, Theta, b3, b5, b7, rcw, rcb, fcw, fcb, gf, bf, out);
}

// round 5
// speedup vs baseline: 1.3827x; 1.0729x over previous
#include <cuda_runtime.h>
#include <cuda_bf16.h>
#include <math.h>

// ---------------- constants ----------------
// B=16, N=1024, T=12, F=1, D_MODEL=512, D_K=D_V=32, H=3, K=3, C=32

// ---------------- scratch (static device memory; no allocation) ----------------
__device__ float g_TEmx[16 * 12 * 1024];      // (B,T,N)
__device__ float g_qkvp[4 * 16 * 12 * 288];   // partial QKV per n-quarter
__device__ float g_qkv [16 * 12 * 288];       // (B,T,288) Q|K|V
__device__ float g_ctx [16 * 12 * 96];        // (B,T,96)
__device__ float g_TAT [16 * 12 * 1024];      // (B,T,N)
__device__ float g_SEmx[16 * 1024 * 512];     // (B,N,512)
__device__ float g_QKs [16 * 1024 * 192];     // (B,N,192): 0..95 = Qs, 96..191 = Ks
__device__ float g_rhs [16 * 3 * 1024 * 12];  // (B,K,N,T)
__device__ unsigned long long g_Wr2[32 * 15 * 32];    // {wa,wb} per (ci,pos,c)
__device__ unsigned long long g_bc [3 * 1024 * 1024]; // {adj*cmask, cheb} per (k,m,j)

// ---------------- f32x2 helpers ----------------
__device__ __forceinline__ unsigned long long pk2(float a, float b) {
    unsigned long long r; asm("mov.b64 %0, {%1,%2};" : "=l"(r) : "f"(a), "f"(b)); return r;
}
__device__ __forceinline__ void unpk(unsigned long long v, float& a, float& b) {
    asm("mov.b64 {%0,%1}, %2;" : "=f"(a), "=f"(b) : "l"(v));
}
__device__ __forceinline__ unsigned long long ffma2(unsigned long long a, unsigned long long b, unsigned long long c) {
    unsigned long long d; asm("fma.rn.f32x2 %0, %1, %2, %3;" : "=l"(d) : "l"(a), "l"(b), "l"(c)); return d;
}
__device__ __forceinline__ unsigned long long mul2(unsigned long long a, unsigned long long b) {
    unsigned long long d; asm("mul.rn.f32x2 %0, %1, %2;" : "=l"(d) : "l"(a), "l"(b)); return d;
}
__device__ __forceinline__ unsigned long long add2(unsigned long long a, unsigned long long b) {
    unsigned long long d; asm("add.rn.f32x2 %0, %1, %2;" : "=l"(d) : "l"(a), "l"(b)); return d;
}

// ---------------- helpers ----------------
__device__ __forceinline__ void block_reduce2(float& s, float& s2, float* shm) {
    #pragma unroll
    for (int o = 16; o > 0; o >>= 1) {
        s  += __shfl_down_sync(0xFFFFFFFFu, s,  o);
        s2 += __shfl_down_sync(0xFFFFFFFFu, s2, o);
    }
    int nw = blockDim.x >> 5;
    int w = threadIdx.x >> 5, l = threadIdx.x & 31;
    if (l == 0) { shm[w] = s; shm[w + 32] = s2; }
    __syncthreads();
    if (w == 0) {
        s  = (l < nw) ? shm[l] : 0.f;
        s2 = (l < nw) ? shm[l + 32] : 0.f;
        #pragma unroll
        for (int o = 16; o > 0; o >>= 1) {
            s  += __shfl_down_sync(0xFFFFFFFFu, s,  o);
            s2 += __shfl_down_sync(0xFFFFFFFFu, s2, o);
        }
        if (l == 0) { shm[0] = s; shm[1] = s2; }
    }
    __syncthreads();
    s = shm[0]; s2 = shm[1];
}

// ---------------- K1: temporal embed + LN over N ----------------
__global__ void k_temporal_ln(const float* __restrict__ x, const float* __restrict__ peT,
                              const float* __restrict__ gT, const float* __restrict__ bT) {
    int b = blockIdx.x / 12, t = blockIdx.x % 12;
    int tid = threadIdx.x;
    __shared__ float shm[64];
    float vals[4]; float s = 0.f, s2 = 0.f;
    #pragma unroll
    for (int i = 0; i < 4; i++) {
        int n = tid + 256 * i;
        float v = x[((size_t)b * 1024 + n) * 12 + t] + peT[t * 1024 + n];
        vals[i] = v; s += v; s2 += v * v;
    }
    block_reduce2(s, s2, shm);
    float mu = s * (1.f / 1024.f);
    float rstd = rsqrtf(s2 * (1.f / 1024.f) - mu * mu + 1e-5f);
    float* op = g_TEmx + ((size_t)b * 12 + t) * 1024;
    #pragma unroll
    for (int i = 0; i < 4; i++) {
        int n = tid + 256 * i;
        op[n] = (vals[i] - mu) * rstd * gT[n] + bT[n];
    }
}

// ---------------- K2a: QKV projection partials; grid (16 b, 4 quarters), 288 thr ----------------
__global__ void k_qkv(const float* __restrict__ WQ, const float* __restrict__ WK,
                      const float* __restrict__ WV) {
    int b = blockIdx.x; int q = blockIdx.y;
    int tid = threadIdx.x;
    int n0 = q * 256;
    __shared__ unsigned long long Ep[6][256];   // pairs (2tp, 2tp+1)
    for (int i = tid; i < 1536; i += 288) {
        int tp = i >> 8; int nn = i & 255;
        float a = g_TEmx[((size_t)b * 12 + 2 * tp) * 1024 + n0 + nn];
        float c = g_TEmx[((size_t)b * 12 + 2 * tp + 1) * 1024 + n0 + nn];
        Ep[tp][nn] = pk2(a, c);
    }
    __syncthreads();
    const float* W; int cw;
    if (tid < 96)       { W = WQ; cw = tid; }
    else if (tid < 192) { W = WK; cw = tid - 96; }
    else                { W = WV; cw = tid - 192; }
    unsigned long long acc[6];
    #pragma unroll
    for (int i = 0; i < 6; i++) acc[i] = 0ull;
    #pragma unroll 4
    for (int nn = 0; nn < 256; nn++) {
        float wv = W[(n0 + nn) * 96 + cw];
        unsigned long long wp = pk2(wv, wv);
        #pragma unroll
        for (int tp = 0; tp < 6; tp++) acc[tp] = ffma2(Ep[tp][nn], wp, acc[tp]);
    }
    int qb = q * 55296 + b * 12 * 288;
    #pragma unroll
    for (int tp = 0; tp < 6; tp++) {
        float lo, hi; unpk(acc[tp], lo, hi);
        g_qkvp[qb + (2 * tp) * 288 + tid]     = lo;
        g_qkvp[qb + (2 * tp + 1) * 288 + tid] = hi;
    }
}

// combine 4 quarters
__global__ void k_qkv2() {
    int idx = blockIdx.x * 256 + threadIdx.x;   // 55296 total
    g_qkv[idx] = g_qkvp[idx] + g_qkvp[idx + 55296] + g_qkvp[idx + 110592] + g_qkvp[idx + 165888];
}

// ---------------- K2b: temporal attention per (b,h); writes re_At ----------------
__global__ void k_tattn(const float* __restrict__ resa, float* __restrict__ reat) {
    int b = blockIdx.x / 3, h = blockIdx.x % 3;
    int tid = threadIdx.x;
    int t = tid >> 5, d = tid & 31;   // 384 threads = 12 warps x 32
    __shared__ float Q[12][32], Kt[12][32], V[12][32], S[12][12];

    const float* qb = g_qkv + ((size_t)b * 12 + t) * 288;
    Q [t][d] = qb[h * 32 + d];
    Kt[t][d] = qb[96 + h * 32 + d];
    V [t][d] = qb[192 + h * 32 + d];
    __syncthreads();

    if (tid < 144) {
        int qi = tid / 12, ki = tid % 12;
        float s = 0.f;
        #pragma unroll
        for (int dd = 0; dd < 32; dd++) s += Q[qi][dd] * Kt[ki][dd];
        s = s * 0.17677669529663687f + resa[((size_t)(b * 3 + h) * 12 + qi) * 12 + ki];
        S[qi][ki] = s;
        reat[((size_t)(b * 3 + h) * 12 + qi) * 12 + ki] = s;
    }
    __syncthreads();
    if (tid < 12) {
        float mxv = -1e30f;
        for (int kx = 0; kx < 12; kx++) mxv = fmaxf(mxv, S[tid][kx]);
        float smv = 0.f;
        for (int kx = 0; kx < 12; kx++) { float pv = __expf(S[tid][kx] - mxv); S[tid][kx] = pv; smv += pv; }
        float inv = 1.f / smv;
        for (int kx = 0; kx < 12; kx++) S[tid][kx] *= inv;
    }
    __syncthreads();
    float cv = 0.f;
    #pragma unroll
    for (int kx = 0; kx < 12; kx++) cv += S[t][kx] * V[kx][d];
    g_ctx[((size_t)b * 12 + t) * 96 + h * 32 + d] = cv;
}

// ---------------- K2c: TATout = LN(ctx @ fc_t + TEmx); 512 threads ----------------
__global__ void k_tatout(const float* __restrict__ fct) {
    int b = blockIdx.x / 12, t = blockIdx.x % 12;
    int tid = threadIdx.x;   // 512, one f32x2 col each
    __shared__ unsigned long long csp[96];
    __shared__ float shm[64];
    if (tid < 96) { float cv = g_ctx[((size_t)b * 12 + t) * 96 + tid]; csp[tid] = pk2(cv, cv); }
    __syncthreads();
    const unsigned long long* Eb2 = (const unsigned long long*)g_TEmx + ((size_t)b * 12 + t) * 512;
    const unsigned long long* fct2 = (const unsigned long long*)fct;
    unsigned long long v = Eb2[tid], u = 0ull;
    #pragma unroll 4
    for (int jx = 0; jx < 96; jx += 2) {
        v = ffma2(csp[jx],     fct2[(size_t)jx * 512 + tid],       v);
        u = ffma2(csp[jx + 1], fct2[(size_t)(jx + 1) * 512 + tid], u);
    }
    v = add2(v, u);
    float a, bv; unpk(v, a, bv);
    float s = a + bv, s2 = a * a + bv * bv;
    block_reduce2(s, s2, shm);
    float mu = s * (1.f / 1024.f);
    float rstd = rsqrtf(s2 * (1.f / 1024.f) - mu * mu + 1e-5f);
    unsigned long long* Tb2 = (unsigned long long*)g_TAT + ((size_t)b * 12 + t) * 512;
    Tb2[tid] = pk2((a - mu) * rstd, (bv - mu) * rstd);
}

// ---------------- K3a: pre_conv + pos_embed_S + LN over 512 -> SEmx ----------------
__global__ void __launch_bounds__(256) k_semx(
        const float* __restrict__ pcw, const float* __restrict__ pcb,
        const float* __restrict__ peS, const float* __restrict__ gS,
        const float* __restrict__ bS) {
    int tid = threadIdx.x;
    int b = blockIdx.x >> 7;
    int n = ((blockIdx.x & 127) << 3) + (tid >> 5);
    int lane = tid & 31;
    __shared__ unsigned long long pcws[12][256];
    #pragma unroll
    for (int t = 0; t < 12; t++)
        pcws[t][tid] = pk2(pcw[(2 * tid) * 12 + t], pcw[(2 * tid + 1) * 12 + t]);
    __syncthreads();

    float tv = 0.f;
    if (lane < 12) tv = g_TAT[((size_t)b * 12 + lane) * 1024 + n];
    unsigned long long ttp[12];
    #pragma unroll
    for (int t = 0; t < 12; t++) {
        float sv = __shfl_sync(0xFFFFFFFFu, tv, t);
        ttp[t] = pk2(sv, sv);
    }
    const unsigned long long* pcb2 = (const unsigned long long*)pcb;
    const unsigned long long* peS2 = (const unsigned long long*)peS + (size_t)n * 256;
    unsigned long long v2[8];
    float s = 0.f, s2 = 0.f;
    #pragma unroll
    for (int i = 0; i < 8; i++) {
        int dp = lane + 32 * i;
        unsigned long long v = add2(pcb2[dp], peS2[dp]);
        #pragma unroll
        for (int t = 0; t < 12; t++) v = ffma2(ttp[t], pcws[t][dp], v);
        v2[i] = v;
        float a, bb; unpk(v, a, bb);
        s += a + bb; s2 += a * a + bb * bb;
    }
    #pragma unroll
    for (int o = 16; o > 0; o >>= 1) {
        s  += __shfl_xor_sync(0xFFFFFFFFu, s,  o);
        s2 += __shfl_xor_sync(0xFFFFFFFFu, s2, o);
    }
    float mu = s * (1.f / 512.f);
    float rstd = rsqrtf(s2 * (1.f / 512.f) - mu * mu + 1e-5f);
    const unsigned long long* g2  = (const unsigned long long*)gS;
    const unsigned long long* bb2 = (const unsigned long long*)bS;
    unsigned long long* o2 = (unsigned long long*)g_SEmx + ((size_t)b * 1024 + n) * 256;
    #pragma unroll
    for (int i = 0; i < 8; i++) {
        int dp = lane + 32 * i;
        float a, bbv; unpk(v2[i], a, bbv);
        float ga, gb; unpk(g2[dp], ga, gb);
        float ba, bx; unpk(bb2[dp], ba, bx);
        o2[dp] = pk2((a - mu) * rstd * ga + ba, (bbv - mu) * rstd * gb + bx);
    }
}

// ---------------- K3b: GEMM QKs = SEmx(16384x512) @ [WQ_s|WK_s](512x192), BN=192 ----------------
__global__ void __launch_bounds__(256) k_qks_gemm(const float* __restrict__ WQ,
                                                  const float* __restrict__ WK) {
    __shared__ __align__(16) float As[16][128];
    __shared__ __align__(16) float Bs[16][192];
    int m0 = blockIdx.x * 128;
    int tid = threadIdx.x;
    int tx = tid % 16, ty = tid / 16;
    unsigned long long acc2[8][6];
    #pragma unroll
    for (int r = 0; r < 8; r++)
        #pragma unroll
        for (int cq = 0; cq < 6; cq++) acc2[r][cq] = 0ull;

    for (int k0 = 0; k0 < 512; k0 += 16) {
        #pragma unroll
        for (int i = 0; i < 2; i++) {
            int e = tid + 256 * i; int m = e >> 2; int kq = (e & 3) * 4;
            float4 a = *(const float4*)&g_SEmx[((size_t)m0 + m) * 512 + k0 + kq];
            As[kq + 0][m] = a.x; As[kq + 1][m] = a.y; As[kq + 2][m] = a.z; As[kq + 3][m] = a.w;
        }
        #pragma unroll
        for (int i = 0; i < 12; i++) {
            int e = tid + 256 * i; int kk = e / 192; int jl = e % 192;
            Bs[kk][jl] = (jl < 96) ? WQ[(k0 + kk) * 96 + jl] : WK[(k0 + kk) * 96 + (jl - 96)];
        }
        __syncthreads();
        #pragma unroll
        for (int kk = 0; kk < 16; kk++) {
            float4 a0 = *(const float4*)&As[kk][ty * 8];
            float4 a1 = *(const float4*)&As[kk][ty * 8 + 4];
            ulonglong2 b01 = *(const ulonglong2*)&Bs[kk][tx * 12];
            ulonglong2 b23 = *(const ulonglong2*)&Bs[kk][tx * 12 + 4];
            ulonglong2 b45 = *(const ulonglong2*)&Bs[kk][tx * 12 + 8];
            unsigned long long bv[6] = {b01.x, b01.y, b23.x, b23.y, b45.x, b45.y};
            float av[8] = {a0.x, a0.y, a0.z, a0.w, a1.x, a1.y, a1.z, a1.w};
            #pragma unroll
            for (int r = 0; r < 8; r++) {
                unsigned long long ap = pk2(av[r], av[r]);
                #pragma unroll
                for (int cq = 0; cq < 6; cq++) acc2[r][cq] = ffma2(ap, bv[cq], acc2[r][cq]);
            }
        }
        __syncthreads();
    }
    #pragma unroll
    for (int r = 0; r < 8; r++) {
        unsigned long long* base = (unsigned long long*)g_QKs + ((size_t)m0 + ty * 8 + r) * 96 + tx * 6;
        *(ulonglong2*)(base)     = make_ulonglong2(acc2[r][0], acc2[r][1]);
        *(ulonglong2*)(base + 2) = make_ulonglong2(acc2[r][2], acc2[r][3]);
        *(ulonglong2*)(base + 4) = make_ulonglong2(acc2[r][4], acc2[r][5]);
    }
}

// ---------------- K3c: precompute {adj*cmask, cheb} packed (2 elems/thread) ----------------
__global__ void k_bc(const float* __restrict__ adj, const float* __restrict__ cmask,
                     const float* __restrict__ cheb) {
    int idx2 = blockIdx.x * 256 + threadIdx.x;   // 1.5M threads, 2 elems each
    int idx = idx2 * 2;
    int mj = idx & 1048575;
    float2 av = *(const float2*)&adj[mj];
    float2 cm = *(const float2*)&cmask[idx];
    float2 cb = *(const float2*)&cheb[idx];
    ulonglong2 o;
    o.x = pk2(av.x * cm.x, cb.x);
    o.y = pk2(av.y * cm.y, cb.y);
    *(ulonglong2*)&g_bc[idx] = o;
}

// ---------------- K4: spatial column-softmax attention (no-max exp; double-buffered) ----------------
__global__ void __launch_bounds__(256) k_spatial(const float* __restrict__ x) {
    int j0 = blockIdx.x * 32; int kk = blockIdx.y; int b = blockIdx.z;
    int tid = threadIdx.x; int lane = tid & 31; int g = tid >> 5;
    int j = j0 + lane;

    const unsigned long long* qk64 = (const unsigned long long*)g_QKs;

    unsigned long long kp[16];
    {
        const ulonglong2* kb = (const ulonglong2*)(qk64 + ((size_t)b * 1024 + j) * 96 + 48 + kk * 16);
        #pragma unroll
        for (int i = 0; i < 8; i++) { ulonglong2 v = kb[i]; kp[2 * i] = v.x; kp[2 * i + 1] = v.y; }
    }

    float sm = 0.f;
    unsigned long long acc[6];
    #pragma unroll
    for (int i = 0; i < 6; i++) acc[i] = 0ull;

    __shared__ __align__(16) unsigned long long Qs64[2][32][16];
    __shared__ unsigned long long xs64[2][32][6];

    const size_t kbase = (size_t)kk << 20;
    const size_t brow = (size_t)b * 1024;

    // preload tile 0
    {
        #pragma unroll
        for (int i = 0; i < 2; i++) {
            int e = tid + 256 * i; int m = e >> 4; int d8 = e & 15;
            Qs64[0][m][d8] = qk64[(brow + m) * 96 + kk * 16 + d8];
        }
        if (tid < 192) {
            int m = tid / 6, i2 = tid % 6;
            xs64[0][m][i2] = ((const unsigned long long*)x)[(brow + m) * 6 + i2];
        }
    }
    __syncthreads();

    for (int it = 0; it < 32; it++) {
        int cur = it & 1;
        unsigned long long pf0 = 0, pf1 = 0, pfx = 0;
        if (it < 31) {
            int m0n = (it + 1) * 32;
            {
                int e = tid; int m = e >> 4; int d8 = e & 15;
                pf0 = qk64[(brow + m0n + m) * 96 + kk * 16 + d8];
            }
            {
                int e = tid + 256; int m = e >> 4; int d8 = e & 15;
                pf1 = qk64[(brow + m0n + m) * 96 + kk * 16 + d8];
            }
            if (tid < 192) {
                int m = tid / 6, i2 = tid % 6;
                pfx = ((const unsigned long long*)x)[(brow + m0n + m) * 6 + i2];
            }
        }

        int m0 = it * 32;
        #pragma unroll
        for (int mi = 0; mi < 4; mi++) {
            int m = g * 4 + mi;
            unsigned long long s2 = 0ull;
            const ulonglong2* qrow = (const ulonglong2*)Qs64[cur][m];
            #pragma unroll
            for (int i = 0; i < 8; i++) {
                ulonglong2 q2 = qrow[i];
                s2 = ffma2(q2.x, kp[2 * i], s2);
                s2 = ffma2(q2.y, kp[2 * i + 1], s2);
            }
            float slo, shi; unpk(s2, slo, shi);
            float bias, cp; unpk(g_bc[kbase + (size_t)(m0 + m) * 1024 + j], bias, cp);
            float s = (slo + shi) * 0.17677669529663687f + bias;
            float p = __expf(s);
            sm += p;
            float w = p * cp;
            unsigned long long wp = pk2(w, w);
            #pragma unroll
            for (int i = 0; i < 6; i++) acc[i] = ffma2(wp, xs64[cur][m][i], acc[i]);
        }

        if (it < 31) {
            int nxt = cur ^ 1;
            {
                int e = tid; Qs64[nxt][e >> 4][e & 15] = pf0;
            }
            {
                int e = tid + 256; Qs64[nxt][e >> 4][e & 15] = pf1;
            }
            if (tid < 192) xs64[nxt][tid / 6][tid % 6] = pfx;
        }
        __syncthreads();
    }

    // merge 8 warp-partials per j (plain sums)
    __shared__ float r_sm[8][32];
    __shared__ unsigned long long r_acc[8][32][6];
    r_sm[g][lane] = sm;
    #pragma unroll
    for (int i = 0; i < 6; i++) r_acc[g][lane][i] = acc[i];
    __syncthreads();
    if (g == 0) {
        float S = 0.f;
        unsigned long long o[6];
        #pragma unroll
        for (int i = 0; i < 6; i++) o[i] = 0ull;
        #pragma unroll
        for (int q = 0; q < 8; q++) {
            S += r_sm[q][lane];
            #pragma unroll
            for (int i = 0; i < 6; i++) o[i] = add2(o[i], r_acc[q][lane][i]);
        }
        float inv = 1.f / S;
        unsigned long long ip = pk2(inv, inv);
        unsigned long long* rp = (unsigned long long*)g_rhs + (((size_t)b * 3 + kk) * 1024 + j) * 6;
        #pragma unroll
        for (int i = 0; i < 6; i++) rp[i] = mul2(o[i], ip);
    }
}

// ---------------- K5: reorder gtu weights to packed {wa,wb} ----------------
__global__ void k_wreorder(const float* __restrict__ w3, const float* __restrict__ w5,
                           const float* __restrict__ w7) {
    int idx = blockIdx.x * 256 + threadIdx.x;
    if (idx >= 15360) return;
    int c = idx & 31; int rest = idx >> 5; int pos = rest % 15; int ci = rest / 15;
    float wa, wb;
    if (pos < 3)      { wa = w3[(c * 32 + ci) * 3 + pos];       wb = w3[((c + 32) * 32 + ci) * 3 + pos]; }
    else if (pos < 8) { wa = w5[(c * 32 + ci) * 5 + (pos - 3)]; wb = w5[((c + 32) * 32 + ci) * 5 + (pos - 3)]; }
    else              { wa = w7[(c * 32 + ci) * 7 + (pos - 8)]; wb = w7[((c + 32) * 32 + ci) * 7 + (pos - 8)]; }
    g_Wr2[(ci * 15 + pos) * 32 + c] = pk2(wa, wb);
}

// ---------------- K6: Theta contraction + GTUs + fcmy + residual + final LN ----------------
__global__ void __launch_bounds__(256) k_gtu(
    const float* __restrict__ x, const float* __restrict__ Theta,
    const float* __restrict__ b3, const float* __restrict__ b5, const float* __restrict__ b7,
    const float* __restrict__ rcw, const float* __restrict__ rcb,
    const float* __restrict__ fcw, const float* __restrict__ fcb,
    const float* __restrict__ gf, const float* __restrict__ bfin,
    float* __restrict__ out) {
    int n0 = blockIdx.x * 8; int b = blockIdx.y;
    int tid = threadIdx.x; int c = tid & 31; int p = tid >> 5; int n = n0 + p;
    __shared__ unsigned long long Xp[8][32][12];
    __shared__ float Vs[8][32][12];
    __shared__ unsigned long long fcw2[24][6];

    if (tid < 144) {
        int w = tid / 6, t2 = tid % 6;
        fcw2[w][t2] = pk2(fcw[w * 12 + 2 * t2], fcw[w * 12 + 2 * t2 + 1]);
    }

    {
        float th0 = Theta[c], th1 = Theta[32 + c], th2 = Theta[64 + c];
        const float* r0 = g_rhs + (((size_t)b * 3 + 0) * 1024 + n) * 12;
        const float* r1 = g_rhs + (((size_t)b * 3 + 1) * 1024 + n) * 12;
        const float* r2 = g_rhs + (((size_t)b * 3 + 2) * 1024 + n) * 12;
        #pragma unroll
        for (int t = 0; t < 12; t++) {
            float v = r0[t] * th0 + r1[t] * th1 + r2[t] * th2;
            v = fmaxf(v, 0.f);
            Xp[p][c][t] = pk2(v, v);
        }
    }
    __syncthreads();

    unsigned long long yab[24];
    {
        unsigned long long i3 = pk2(b3[c], b3[c + 32]);
        unsigned long long i5 = pk2(b5[c], b5[c + 32]);
        unsigned long long i7 = pk2(b7[c], b7[c + 32]);
        #pragma unroll
        for (int w = 0; w < 10; w++) yab[w] = i3;
        #pragma unroll
        for (int w = 0; w < 8; w++)  yab[10 + w] = i5;
        #pragma unroll
        for (int w = 0; w < 6; w++)  yab[18 + w] = i7;
    }

    for (int ci = 0; ci < 32; ci++) {
        unsigned long long Xr[12];
        #pragma unroll
        for (int t = 0; t < 12; t++) Xr[t] = Xp[p][ci][t];
        const unsigned long long* wr = g_Wr2 + (size_t)ci * 15 * 32 + c;
        #pragma unroll
        for (int dt = 0; dt < 3; dt++) {
            unsigned long long wv = wr[dt * 32];
            #pragma unroll
            for (int w = 0; w < 10; w++) yab[w] = ffma2(Xr[w + dt], wv, yab[w]);
        }
        #pragma unroll
        for (int dt = 0; dt < 5; dt++) {
            unsigned long long wv = wr[(3 + dt) * 32];
            #pragma unroll
            for (int w = 0; w < 8; w++) yab[10 + w] = ffma2(Xr[w + dt], wv, yab[10 + w]);
        }
        #pragma unroll
        for (int dt = 0; dt < 7; dt++) {
            unsigned long long wv = wr[(8 + dt) * 32];
            #pragma unroll
            for (int w = 0; w < 6; w++) yab[18 + w] = ffma2(Xr[w + dt], wv, yab[18 + w]);
        }
    }

    unsigned long long v2[6];
    {
        const unsigned long long* fcb2 = (const unsigned long long*)fcb;
        #pragma unroll
        for (int t2 = 0; t2 < 6; t2++) v2[t2] = fcb2[t2];
    }
    #pragma unroll
    for (int w = 0; w < 24; w++) {
        float ya, yb; unpk(yab[w], ya, yb);
        float tv = 1.f - 2.f / (__expf(2.f * ya) + 1.f);
        float sg = 1.f / (1.f + __expf(-yb));
        float gv = tv * sg;
        unsigned long long gp = pk2(gv, gv);
        #pragma unroll
        for (int t2 = 0; t2 < 6; t2++) v2[t2] = ffma2(gp, fcw2[w][t2], v2[t2]);
    }

    float rw = rcw[c], rb = rcb[c];
    const unsigned long long* xp2 = (const unsigned long long*)x + ((size_t)b * 1024 + n) * 6;
    #pragma unroll
    for (int t2 = 0; t2 < 6; t2++) {
        float va, vb; unpk(v2[t2], va, vb);
        float xa, xb; unpk(xp2[t2], xa, xb);
        va = fmaxf(va, 0.f); vb = fmaxf(vb, 0.f);
        Vs[p][c][2 * t2]     = fmaxf(xa * rw + rb + va, 0.f);
        Vs[p][c][2 * t2 + 1] = fmaxf(xb * rw + rb + vb, 0.f);
    }
    __syncthreads();

    if (tid < 96) {
        int p2 = tid / 12, t2 = tid % 12;
        float s = 0.f, s2 = 0.f;
        #pragma unroll
        for (int cc = 0; cc < 32; cc++) { float v = Vs[p2][cc][t2]; s += v; s2 += v * v; }
        float mu = s * (1.f / 32.f);
        float var = s2 * (1.f / 32.f) - mu * mu;
        float rstd = rsqrtf(var + 1e-5f);
        float* op = out + (((size_t)b * 1024 + n0 + p2) * 32) * 12 + t2;
        #pragma unroll
        for (int cc = 0; cc < 32; cc++)
            op[cc * 12] = (Vs[p2][cc][t2] - mu) * rstd * gf[cc] + bfin[cc];
    }
}

// ---------------- launch ----------------
extern "C" void kernel_launch(void* const* d_in, const int* in_sizes, int n_in,
                              void* d_out, int out_size) {
    const float* x     = (const float*)d_in[0];
    const float* resa  = (const float*)d_in[1];
    const float* peT   = (const float*)d_in[2];
    const float* gT    = (const float*)d_in[3];
    const float* bT    = (const float*)d_in[4];
    const float* WQt   = (const float*)d_in[5];
    const float* WKt   = (const float*)d_in[6];
    const float* WVt   = (const float*)d_in[7];
    const float* fct   = (const float*)d_in[8];
    const float* pcw   = (const float*)d_in[9];
    const float* pcb   = (const float*)d_in[10];
    const float* peS   = (const float*)d_in[11];
    const float* gS    = (const float*)d_in[12];
    const float* bS    = (const float*)d_in[13];
    const float* WQs   = (const float*)d_in[14];
    const float* WKs   = (const float*)d_in[15];
    const float* cheb  = (const float*)d_in[16];
    const float* adj   = (const float*)d_in[17];
    const float* cmask = (const float*)d_in[18];
    const float* Theta = (const float*)d_in[19];
    const float* w3    = (const float*)d_in[20];
    const float* b3    = (const float*)d_in[21];
    const float* w5    = (const float*)d_in[22];
    const float* b5    = (const float*)d_in[23];
    const float* w7    = (const float*)d_in[24];
    const float* b7    = (const float*)d_in[25];
    const float* rcw   = (const float*)d_in[26];
    const float* rcb   = (const float*)d_in[27];
    const float* fcw   = (const float*)d_in[28];
    const float* fcb   = (const float*)d_in[29];
    const float* gf    = (const float*)d_in[30];
    const float* bf    = (const float*)d_in[31];

    float* out  = (float*)d_out;
    float* reat = out + (size_t)16 * 1024 * 32 * 12;  // re_At after main output

    k_temporal_ln<<<192, 256>>>(x, peT, gT, bT);
    k_qkv<<<dim3(16, 4), 288>>>(WQt, WKt, WVt);
    k_qkv2<<<216, 256>>>();
    k_tattn<<<48, 384>>>(resa, reat);
    k_tatout<<<192, 512>>>(fct);
    k_semx<<<2048, 256>>>(pcw, pcb, peS, gS, bS);
    k_qks_gemm<<<128, 256>>>(WQs, WKs);
    k_wreorder<<<60, 256>>>(w3, w5, w7);
    k_bc<<<6144, 256>>>(adj, cmask, cheb);
    k_spatial<<<dim3(32, 3, 16), 256>>>(x);
    k_gtu<<<dim3(128, 16), 256>>>(x, Theta, b3, b5, b7, rcw, rcb, fcw, fcb, gf, bf, out);
}

// round 6
// speedup vs baseline: 1.4155x; 1.0237x over previous
#include <cuda_runtime.h>
#include <cuda_bf16.h>
#include <math.h>

// ---------------- constants ----------------
// B=16, N=1024, T=12, F=1, D_MODEL=512, D_K=D_V=32, H=3, K=3, C=32

// ---------------- scratch (static device memory; no allocation) ----------------
__device__ float g_TEmx[16 * 12 * 1024];      // (B,T,N)
__device__ float g_qkvp[4 * 16 * 12 * 288];   // partial QKV per n-quarter
__device__ float g_ctx [16 * 12 * 96];        // (B,T,96)
__device__ float g_TAT [16 * 12 * 1024];      // (B,T,N)
__device__ float g_SEmx[16 * 1024 * 512];     // (B,N,512)
__device__ float g_QKs [16 * 1024 * 192];     // (B,N,192): 0..95 = Qs, 96..191 = Ks
__device__ float g_rhs [16 * 3 * 1024 * 12];  // (B,K,N,T)
__device__ unsigned long long g_Wr2[32 * 15 * 32];    // {wa,wb} per (ci,pos,c)
__device__ unsigned long long g_bc [3 * 1024 * 1024]; // {adj*cmask, cheb} per (k,m,j)
__device__ unsigned long long g_part[2 * 7 * 49152];  // spatial partials [half][slot][jidx]

// ---------------- f32x2 helpers ----------------
__device__ __forceinline__ unsigned long long pk2(float a, float b) {
    unsigned long long r; asm("mov.b64 %0, {%1,%2};" : "=l"(r) : "f"(a), "f"(b)); return r;
}
__device__ __forceinline__ void unpk(unsigned long long v, float& a, float& b) {
    asm("mov.b64 {%0,%1}, %2;" : "=f"(a), "=f"(b) : "l"(v));
}
__device__ __forceinline__ unsigned long long ffma2(unsigned long long a, unsigned long long b, unsigned long long c) {
    unsigned long long d; asm("fma.rn.f32x2 %0, %1, %2, %3;" : "=l"(d) : "l"(a), "l"(b), "l"(c)); return d;
}
__device__ __forceinline__ unsigned long long mul2(unsigned long long a, unsigned long long b) {
    unsigned long long d; asm("mul.rn.f32x2 %0, %1, %2;" : "=l"(d) : "l"(a), "l"(b)); return d;
}
__device__ __forceinline__ unsigned long long add2(unsigned long long a, unsigned long long b) {
    unsigned long long d; asm("add.rn.f32x2 %0, %1, %2;" : "=l"(d) : "l"(a), "l"(b)); return d;
}

// ---------------- helpers ----------------
__device__ __forceinline__ void block_reduce2(float& s, float& s2, float* shm) {
    #pragma unroll
    for (int o = 16; o > 0; o >>= 1) {
        s  += __shfl_down_sync(0xFFFFFFFFu, s,  o);
        s2 += __shfl_down_sync(0xFFFFFFFFu, s2, o);
    }
    int nw = blockDim.x >> 5;
    int w = threadIdx.x >> 5, l = threadIdx.x & 31;
    if (l == 0) { shm[w] = s; shm[w + 32] = s2; }
    __syncthreads();
    if (w == 0) {
        s  = (l < nw) ? shm[l] : 0.f;
        s2 = (l < nw) ? shm[l + 32] : 0.f;
        #pragma unroll
        for (int o = 16; o > 0; o >>= 1) {
            s  += __shfl_down_sync(0xFFFFFFFFu, s,  o);
            s2 += __shfl_down_sync(0xFFFFFFFFu, s2, o);
        }
        if (l == 0) { shm[0] = s; shm[1] = s2; }
    }
    __syncthreads();
    s = shm[0]; s2 = shm[1];
}

// ---------------- K1: temporal embed + LN over N ----------------
__global__ void k_temporal_ln(const float* __restrict__ x, const float* __restrict__ peT,
                              const float* __restrict__ gT, const float* __restrict__ bT) {
    int b = blockIdx.x / 12, t = blockIdx.x % 12;
    int tid = threadIdx.x;
    __shared__ float shm[64];
    float vals[4]; float s = 0.f, s2 = 0.f;
    #pragma unroll
    for (int i = 0; i < 4; i++) {
        int n = tid + 256 * i;
        float v = x[((size_t)b * 1024 + n) * 12 + t] + peT[t * 1024 + n];
        vals[i] = v; s += v; s2 += v * v;
    }
    block_reduce2(s, s2, shm);
    float mu = s * (1.f / 1024.f);
    float rstd = rsqrtf(s2 * (1.f / 1024.f) - mu * mu + 1e-5f);
    float* op = g_TEmx + ((size_t)b * 12 + t) * 1024;
    #pragma unroll
    for (int i = 0; i < 4; i++) {
        int n = tid + 256 * i;
        op[n] = (vals[i] - mu) * rstd * gT[n] + bT[n];
    }
}

// ---------------- K2a: QKV projection partials; grid (16 b, 4 quarters), 288 thr ----------------
__global__ void k_qkv(const float* __restrict__ WQ, const float* __restrict__ WK,
                      const float* __restrict__ WV) {
    int b = blockIdx.x; int q = blockIdx.y;
    int tid = threadIdx.x;
    int n0 = q * 256;
    __shared__ unsigned long long Ep[6][256];   // pairs (2tp, 2tp+1)
    for (int i = tid; i < 1536; i += 288) {
        int tp = i >> 8; int nn = i & 255;
        float a = g_TEmx[((size_t)b * 12 + 2 * tp) * 1024 + n0 + nn];
        float c = g_TEmx[((size_t)b * 12 + 2 * tp + 1) * 1024 + n0 + nn];
        Ep[tp][nn] = pk2(a, c);
    }
    __syncthreads();
    const float* W; int cw;
    if (tid < 96)       { W = WQ; cw = tid; }
    else if (tid < 192) { W = WK; cw = tid - 96; }
    else                { W = WV; cw = tid - 192; }
    unsigned long long acc[6];
    #pragma unroll
    for (int i = 0; i < 6; i++) acc[i] = 0ull;
    #pragma unroll 4
    for (int nn = 0; nn < 256; nn++) {
        float wv = W[(n0 + nn) * 96 + cw];
        unsigned long long wp = pk2(wv, wv);
        #pragma unroll
        for (int tp = 0; tp < 6; tp++) acc[tp] = ffma2(Ep[tp][nn], wp, acc[tp]);
    }
    int qb = q * 55296 + b * 12 * 288;
    #pragma unroll
    for (int tp = 0; tp < 6; tp++) {
        float lo, hi; unpk(acc[tp], lo, hi);
        g_qkvp[qb + (2 * tp) * 288 + tid]     = lo;
        g_qkvp[qb + (2 * tp + 1) * 288 + tid] = hi;
    }
}

// ---------------- K2b: temporal attention per (b,h); sums quarter-partials; writes re_At ----------------
__global__ void k_tattn(const float* __restrict__ resa, float* __restrict__ reat) {
    int b = blockIdx.x / 3, h = blockIdx.x % 3;
    int tid = threadIdx.x;
    int t = tid >> 5, d = tid & 31;   // 384 threads = 12 warps x 32
    __shared__ float Q[12][32], Kt[12][32], V[12][32], S[12][12];

    int off = b * 3456 + t * 288 + h * 32 + d;
    Q [t][d] = g_qkvp[off]       + g_qkvp[off + 55296]       + g_qkvp[off + 110592]       + g_qkvp[off + 165888];
    Kt[t][d] = g_qkvp[off + 96]  + g_qkvp[off + 96 + 55296]  + g_qkvp[off + 96 + 110592]  + g_qkvp[off + 96 + 165888];
    V [t][d] = g_qkvp[off + 192] + g_qkvp[off + 192 + 55296] + g_qkvp[off + 192 + 110592] + g_qkvp[off + 192 + 165888];
    __syncthreads();

    if (tid < 144) {
        int qi = tid / 12, ki = tid % 12;
        float s = 0.f;
        #pragma unroll
        for (int dd = 0; dd < 32; dd++) s += Q[qi][dd] * Kt[ki][dd];
        s = s * 0.17677669529663687f + resa[((size_t)(b * 3 + h) * 12 + qi) * 12 + ki];
        S[qi][ki] = s;
        reat[((size_t)(b * 3 + h) * 12 + qi) * 12 + ki] = s;
    }
    __syncthreads();
    if (tid < 12) {
        float mxv = -1e30f;
        for (int kx = 0; kx < 12; kx++) mxv = fmaxf(mxv, S[tid][kx]);
        float smv = 0.f;
        for (int kx = 0; kx < 12; kx++) { float pv = __expf(S[tid][kx] - mxv); S[tid][kx] = pv; smv += pv; }
        float inv = 1.f / smv;
        for (int kx = 0; kx < 12; kx++) S[tid][kx] *= inv;
    }
    __syncthreads();
    float cv = 0.f;
    #pragma unroll
    for (int kx = 0; kx < 12; kx++) cv += S[t][kx] * V[kx][d];
    g_ctx[((size_t)b * 12 + t) * 96 + h * 32 + d] = cv;
}

// ---------------- K2c: TATout = LN(ctx @ fc_t + TEmx); 512 threads ----------------
__global__ void k_tatout(const float* __restrict__ fct) {
    int b = blockIdx.x / 12, t = blockIdx.x % 12;
    int tid = threadIdx.x;   // 512, one f32x2 col each
    __shared__ unsigned long long csp[96];
    __shared__ float shm[64];
    if (tid < 96) { float cv = g_ctx[((size_t)b * 12 + t) * 96 + tid]; csp[tid] = pk2(cv, cv); }
    __syncthreads();
    const unsigned long long* Eb2 = (const unsigned long long*)g_TEmx + ((size_t)b * 12 + t) * 512;
    const unsigned long long* fct2 = (const unsigned long long*)fct;
    unsigned long long v = Eb2[tid], u = 0ull;
    #pragma unroll 4
    for (int jx = 0; jx < 96; jx += 2) {
        v = ffma2(csp[jx],     fct2[(size_t)jx * 512 + tid],       v);
        u = ffma2(csp[jx + 1], fct2[(size_t)(jx + 1) * 512 + tid], u);
    }
    v = add2(v, u);
    float a, bv; unpk(v, a, bv);
    float s = a + bv, s2 = a * a + bv * bv;
    block_reduce2(s, s2, shm);
    float mu = s * (1.f / 1024.f);
    float rstd = rsqrtf(s2 * (1.f / 1024.f) - mu * mu + 1e-5f);
    unsigned long long* Tb2 = (unsigned long long*)g_TAT + ((size_t)b * 12 + t) * 512;
    Tb2[tid] = pk2((a - mu) * rstd, (bv - mu) * rstd);
}

// ---------------- K3a: pre_conv + pos_embed_S + LN over 512 -> SEmx ----------------
__global__ void __launch_bounds__(256) k_semx(
        const float* __restrict__ pcw, const float* __restrict__ pcb,
        const float* __restrict__ peS, const float* __restrict__ gS,
        const float* __restrict__ bS) {
    int tid = threadIdx.x;
    int b = blockIdx.x >> 7;
    int n = ((blockIdx.x & 127) << 3) + (tid >> 5);
    int lane = tid & 31;
    __shared__ unsigned long long pcws[12][256];
    #pragma unroll
    for (int t = 0; t < 12; t++)
        pcws[t][tid] = pk2(pcw[(2 * tid) * 12 + t], pcw[(2 * tid + 1) * 12 + t]);
    __syncthreads();

    float tv = 0.f;
    if (lane < 12) tv = g_TAT[((size_t)b * 12 + lane) * 1024 + n];
    unsigned long long ttp[12];
    #pragma unroll
    for (int t = 0; t < 12; t++) {
        float sv = __shfl_sync(0xFFFFFFFFu, tv, t);
        ttp[t] = pk2(sv, sv);
    }
    const unsigned long long* pcb2 = (const unsigned long long*)pcb;
    const unsigned long long* peS2 = (const unsigned long long*)peS + (size_t)n * 256;
    unsigned long long v2[8];
    float s = 0.f, s2 = 0.f;
    #pragma unroll
    for (int i = 0; i < 8; i++) {
        int dp = lane + 32 * i;
        unsigned long long v = add2(pcb2[dp], peS2[dp]);
        #pragma unroll
        for (int t = 0; t < 12; t++) v = ffma2(ttp[t], pcws[t][dp], v);
        v2[i] = v;
        float a, bb; unpk(v, a, bb);
        s += a + bb; s2 += a * a + bb * bb;
    }
    #pragma unroll
    for (int o = 16; o > 0; o >>= 1) {
        s  += __shfl_xor_sync(0xFFFFFFFFu, s,  o);
        s2 += __shfl_xor_sync(0xFFFFFFFFu, s2, o);
    }
    float mu = s * (1.f / 512.f);
    float rstd = rsqrtf(s2 * (1.f / 512.f) - mu * mu + 1e-5f);
    const unsigned long long* g2  = (const unsigned long long*)gS;
    const unsigned long long* bb2 = (const unsigned long long*)bS;
    unsigned long long* o2 = (unsigned long long*)g_SEmx + ((size_t)b * 1024 + n) * 256;
    #pragma unroll
    for (int i = 0; i < 8; i++) {
        int dp = lane + 32 * i;
        float a, bbv; unpk(v2[i], a, bbv);
        float ga, gb; unpk(g2[dp], ga, gb);
        float ba, bx; unpk(bb2[dp], ba, bx);
        o2[dp] = pk2((a - mu) * rstd * ga + ba, (bbv - mu) * rstd * gb + bx);
    }
}

// ---------------- K3b: GEMM QKs = SEmx(16384x512) @ [WQ_s|WK_s](512x192), BM=64 ----------------
__global__ void __launch_bounds__(256) k_qks_gemm(const float* __restrict__ WQ,
                                                  const float* __restrict__ WK) {
    __shared__ __align__(16) float As[16][64];
    __shared__ __align__(16) float Bs[16][192];
    int m0 = blockIdx.x * 64;
    int tid = threadIdx.x;
    int tx = tid % 16, ty = tid / 16;
    unsigned long long acc2[4][6];
    #pragma unroll
    for (int r = 0; r < 4; r++)
        #pragma unroll
        for (int cq = 0; cq < 6; cq++) acc2[r][cq] = 0ull;

    for (int k0 = 0; k0 < 512; k0 += 16) {
        {
            int m = tid >> 2; int kq = (tid & 3) * 4;
            float4 a = *(const float4*)&g_SEmx[((size_t)m0 + m) * 512 + k0 + kq];
            As[kq + 0][m] = a.x; As[kq + 1][m] = a.y; As[kq + 2][m] = a.z; As[kq + 3][m] = a.w;
        }
        #pragma unroll
        for (int i = 0; i < 12; i++) {
            int e = tid + 256 * i; int kk = e / 192; int jl = e % 192;
            Bs[kk][jl] = (jl < 96) ? WQ[(k0 + kk) * 96 + jl] : WK[(k0 + kk) * 96 + (jl - 96)];
        }
        __syncthreads();
        #pragma unroll
        for (int kk = 0; kk < 16; kk++) {
            float4 a0 = *(const float4*)&As[kk][ty * 4];
            ulonglong2 b01 = *(const ulonglong2*)&Bs[kk][tx * 12];
            ulonglong2 b23 = *(const ulonglong2*)&Bs[kk][tx * 12 + 4];
            ulonglong2 b45 = *(const ulonglong2*)&Bs[kk][tx * 12 + 8];
            unsigned long long bv[6] = {b01.x, b01.y, b23.x, b23.y, b45.x, b45.y};
            float av[4] = {a0.x, a0.y, a0.z, a0.w};
            #pragma unroll
            for (int r = 0; r < 4; r++) {
                unsigned long long ap = pk2(av[r], av[r]);
                #pragma unroll
                for (int cq = 0; cq < 6; cq++) acc2[r][cq] = ffma2(ap, bv[cq], acc2[r][cq]);
            }
        }
        __syncthreads();
    }
    #pragma unroll
    for (int r = 0; r < 4; r++) {
        unsigned long long* base = (unsigned long long*)g_QKs + ((size_t)m0 + ty * 4 + r) * 96 + tx * 6;
        *(ulonglong2*)(base)     = make_ulonglong2(acc2[r][0], acc2[r][1]);
        *(ulonglong2*)(base + 2) = make_ulonglong2(acc2[r][2], acc2[r][3]);
        *(ulonglong2*)(base + 4) = make_ulonglong2(acc2[r][4], acc2[r][5]);
    }
}

// ---------------- K3c: prep = {adj*cmask, cheb} pack  +  gtu weight reorder ----------------
__global__ void k_prep(const float* __restrict__ adj, const float* __restrict__ cmask,
                       const float* __restrict__ cheb,
                       const float* __restrict__ w3, const float* __restrict__ w5,
                       const float* __restrict__ w7) {
    if (blockIdx.x < 6144) {
        int idx2 = blockIdx.x * 256 + threadIdx.x;   // 1.5M threads, 2 elems each
        int idx = idx2 * 2;
        int mj = idx & 1048575;
        float2 av = *(const float2*)&adj[mj];
        float2 cm = *(const float2*)&cmask[idx];
        float2 cb = *(const float2*)&cheb[idx];
        ulonglong2 o;
        o.x = pk2(av.x * cm.x, cb.x);
        o.y = pk2(av.y * cm.y, cb.y);
        *(ulonglong2*)&g_bc[idx] = o;
    } else {
        int idx = (blockIdx.x - 6144) * 256 + threadIdx.x;
        if (idx >= 15360) return;
        int c = idx & 31; int rest = idx >> 5; int pos = rest % 15; int ci = rest / 15;
        float wa, wb;
        if (pos < 3)      { wa = w3[(c * 32 + ci) * 3 + pos];       wb = w3[((c + 32) * 32 + ci) * 3 + pos]; }
        else if (pos < 8) { wa = w5[(c * 32 + ci) * 5 + (pos - 3)]; wb = w5[((c + 32) * 32 + ci) * 5 + (pos - 3)]; }
        else              { wa = w7[(c * 32 + ci) * 7 + (pos - 8)]; wb = w7[((c + 32) * 32 + ci) * 7 + (pos - 8)]; }
        g_Wr2[(ci * 15 + pos) * 32 + c] = pk2(wa, wb);
    }
}

// ---------------- K4: spatial column-softmax attention (m-split x2, bc reg-prefetch) ----------------
__global__ void __launch_bounds__(256) k_spatial(const float* __restrict__ x) {
    int j0 = blockIdx.x * 32; int kk = blockIdx.y;
    int b = blockIdx.z >> 1; int half = blockIdx.z & 1;
    int tid = threadIdx.x; int lane = tid & 31; int g = tid >> 5;
    int j = j0 + lane;

    const unsigned long long* qk64 = (const unsigned long long*)g_QKs;

    unsigned long long kp[16];
    {
        const ulonglong2* kb = (const ulonglong2*)(qk64 + ((size_t)b * 1024 + j) * 96 + 48 + kk * 16);
        #pragma unroll
        for (int i = 0; i < 8; i++) { ulonglong2 v = kb[i]; kp[2 * i] = v.x; kp[2 * i + 1] = v.y; }
    }

    float sm = 0.f;
    unsigned long long acc[6];
    #pragma unroll
    for (int i = 0; i < 6; i++) acc[i] = 0ull;

    __shared__ __align__(16) unsigned long long Qs64[2][32][16];
    __shared__ unsigned long long xs64[2][32][6];

    const size_t kbase = (size_t)kk << 20;
    const size_t brow = (size_t)b * 1024;
    const int mbase = half * 512;

    // preload tile 0
    {
        #pragma unroll
        for (int i = 0; i < 2; i++) {
            int e = tid + 256 * i; int m = e >> 4; int d8 = e & 15;
            Qs64[0][m][d8] = qk64[(brow + mbase + m) * 96 + kk * 16 + d8];
        }
        if (tid < 192) {
            int m = tid / 6, i2 = tid % 6;
            xs64[0][m][i2] = ((const unsigned long long*)x)[(brow + mbase + m) * 6 + i2];
        }
    }
    // preload bc for it=0
    unsigned long long bcur[4];
    #pragma unroll
    for (int mi = 0; mi < 4; mi++)
        bcur[mi] = g_bc[kbase + (size_t)(mbase + g * 4 + mi) * 1024 + j];
    __syncthreads();

    for (int it = 0; it < 16; it++) {
        int cur = it & 1;
        unsigned long long pf0 = 0, pf1 = 0, pfx = 0, bnxt[4];
        if (it < 15) {
            int m0n = mbase + (it + 1) * 32;
            {
                int e = tid; int m = e >> 4; int d8 = e & 15;
                pf0 = qk64[(brow + m0n + m) * 96 + kk * 16 + d8];
            }
            {
                int e = tid + 256; int m = e >> 4; int d8 = e & 15;
                pf1 = qk64[(brow + m0n + m) * 96 + kk * 16 + d8];
            }
            if (tid < 192) {
                int m = tid / 6, i2 = tid % 6;
                pfx = ((const unsigned long long*)x)[(brow + m0n + m) * 6 + i2];
            }
            #pragma unroll
            for (int mi = 0; mi < 4; mi++)
                bnxt[mi] = g_bc[kbase + (size_t)(m0n + g * 4 + mi) * 1024 + j];
        }

        #pragma unroll
        for (int mi = 0; mi < 4; mi++) {
            int m = g * 4 + mi;
            unsigned long long s2 = 0ull;
            const ulonglong2* qrow = (const ulonglong2*)Qs64[cur][m];
            #pragma unroll
            for (int i = 0; i < 8; i++) {
                ulonglong2 q2 = qrow[i];
                s2 = ffma2(q2.x, kp[2 * i], s2);
                s2 = ffma2(q2.y, kp[2 * i + 1], s2);
            }
            float slo, shi; unpk(s2, slo, shi);
            float bias, cp; unpk(bcur[mi], bias, cp);
            float s = (slo + shi) * 0.17677669529663687f + bias;
            float p = __expf(s);
            sm += p;
            float w = p * cp;
            unsigned long long wp = pk2(w, w);
            #pragma unroll
            for (int i = 0; i < 6; i++) acc[i] = ffma2(wp, xs64[cur][m][i], acc[i]);
        }

        if (it < 15) {
            int nxt = cur ^ 1;
            { int e = tid;       Qs64[nxt][e >> 4][e & 15] = pf0; }
            { int e = tid + 256; Qs64[nxt][e >> 4][e & 15] = pf1; }
            if (tid < 192) xs64[nxt][tid / 6][tid % 6] = pfx;
            #pragma unroll
            for (int mi = 0; mi < 4; mi++) bcur[mi] = bnxt[mi];
        }
        __syncthreads();
    }

    // merge 8 warp-partials per j; write unnormalized partials for this half
    __shared__ float r_sm[8][32];
    __shared__ unsigned long long r_acc[8][32][6];
    r_sm[g][lane] = sm;
    #pragma unroll
    for (int i = 0; i < 6; i++) r_acc[g][lane][i] = acc[i];
    __syncthreads();
    if (g == 0) {
        float S = 0.f;
        unsigned long long o[6];
        #pragma unroll
        for (int i = 0; i < 6; i++) o[i] = 0ull;
        #pragma unroll
        for (int q = 0; q < 8; q++) {
            S += r_sm[q][lane];
            #pragma unroll
            for (int i = 0; i < 6; i++) o[i] = add2(o[i], r_acc[q][lane][i]);
        }
        int jidx = ((b * 3 + kk) << 10) + j;
        unsigned long long* pp = g_part + (size_t)half * 7 * 49152;
        #pragma unroll
        for (int i = 0; i < 6; i++) pp[i * 49152 + jidx] = o[i];
        pp[6 * 49152 + jidx] = pk2(S, S);
    }
}

// ---------------- K4b: merge the two m-halves, normalize ----------------
__global__ void k_smerge() {
    int jidx = blockIdx.x * 256 + threadIdx.x;   // 49152
    unsigned long long o[6];
    float S = 0.f;
    #pragma unroll
    for (int i = 0; i < 6; i++) o[i] = 0ull;
    #pragma unroll
    for (int half = 0; half < 2; half++) {
        const unsigned long long* pp = g_part + (size_t)half * 7 * 49152;
        float sl, sh; unpk(pp[6 * 49152 + jidx], sl, sh);
        S += sl;
        #pragma unroll
        for (int i = 0; i < 6; i++) o[i] = add2(o[i], pp[i * 49152 + jidx]);
    }
    float inv = 1.f / S;
    unsigned long long ip = pk2(inv, inv);
    unsigned long long* rp = (unsigned long long*)g_rhs + (size_t)jidx * 6;
    #pragma unroll
    for (int i = 0; i < 6; i++) rp[i] = mul2(o[i], ip);
}

// ---------------- K6: Theta contraction + GTUs + fcmy + residual + final LN ----------------
__global__ void __launch_bounds__(256) k_gtu(
    const float* __restrict__ x, const float* __restrict__ Theta,
    const float* __restrict__ b3, const float* __restrict__ b5, const float* __restrict__ b7,
    const float* __restrict__ rcw, const float* __restrict__ rcb,
    const float* __restrict__ fcw, const float* __restrict__ fcb,
    const float* __restrict__ gf, const float* __restrict__ bfin,
    float* __restrict__ out) {
    int n0 = blockIdx.x * 8; int b = blockIdx.y;
    int tid = threadIdx.x; int c = tid & 31; int p = tid >> 5; int n = n0 + p;
    __shared__ unsigned long long Xp[8][32][12];
    __shared__ float Vs[8][32][12];
    __shared__ unsigned long long fcw2[24][6];

    if (tid < 144) {
        int w = tid / 6, t2 = tid % 6;
        fcw2[w][t2] = pk2(fcw[w * 12 + 2 * t2], fcw[w * 12 + 2 * t2 + 1]);
    }

    {
        float th0 = Theta[c], th1 = Theta[32 + c], th2 = Theta[64 + c];
        const float* r0 = g_rhs + (((size_t)b * 3 + 0) * 1024 + n) * 12;
        const float* r1 = g_rhs + (((size_t)b * 3 + 1) * 1024 + n) * 12;
        const float* r2 = g_rhs + (((size_t)b * 3 + 2) * 1024 + n) * 12;
        #pragma unroll
        for (int t = 0; t < 12; t++) {
            float v = r0[t] * th0 + r1[t] * th1 + r2[t] * th2;
            v = fmaxf(v, 0.f);
            Xp[p][c][t] = pk2(v, v);
        }
    }
    __syncthreads();

    unsigned long long yab[24];
    {
        unsigned long long i3 = pk2(b3[c], b3[c + 32]);
        unsigned long long i5 = pk2(b5[c], b5[c + 32]);
        unsigned long long i7 = pk2(b7[c], b7[c + 32]);
        #pragma unroll
        for (int w = 0; w < 10; w++) yab[w] = i3;
        #pragma unroll
        for (int w = 0; w < 8; w++)  yab[10 + w] = i5;
        #pragma unroll
        for (int w = 0; w < 6; w++)  yab[18 + w] = i7;
    }

    for (int ci = 0; ci < 32; ci++) {
        unsigned long long Xr[12];
        #pragma unroll
        for (int t = 0; t < 12; t++) Xr[t] = Xp[p][ci][t];
        const unsigned long long* wr = g_Wr2 + (size_t)ci * 15 * 32 + c;
        #pragma unroll
        for (int dt = 0; dt < 3; dt++) {
            unsigned long long wv = __ldg(&wr[dt * 32]);
            #pragma unroll
            for (int w = 0; w < 10; w++) yab[w] = ffma2(Xr[w + dt], wv, yab[w]);
        }
        #pragma unroll
        for (int dt = 0; dt < 5; dt++) {
            unsigned long long wv = __ldg(&wr[(3 + dt) * 32]);
            #pragma unroll
            for (int w = 0; w < 8; w++) yab[10 + w] = ffma2(Xr[w + dt], wv, yab[10 + w]);
        }
        #pragma unroll
        for (int dt = 0; dt < 7; dt++) {
            unsigned long long wv = __ldg(&wr[(8 + dt) * 32]);
            #pragma unroll
            for (int w = 0; w < 6; w++) yab[18 + w] = ffma2(Xr[w + dt], wv, yab[18 + w]);
        }
    }

    unsigned long long v2[6];
    {
        const unsigned long long* fcb2 = (const unsigned long long*)fcb;
        #pragma unroll
        for (int t2 = 0; t2 < 6; t2++) v2[t2] = fcb2[t2];
    }
    #pragma unroll
    for (int w = 0; w < 24; w++) {
        float ya, yb; unpk(yab[w], ya, yb);
        float tv = 1.f - 2.f / (__expf(2.f * ya) + 1.f);
        float sg = 1.f / (1.f + __expf(-yb));
        float gv = tv * sg;
        unsigned long long gp = pk2(gv, gv);
        #pragma unroll
        for (int t2 = 0; t2 < 6; t2++) v2[t2] = ffma2(gp, fcw2[w][t2], v2[t2]);
    }

    float rw = rcw[c], rb = rcb[c];
    const unsigned long long* xp2 = (const unsigned long long*)x + ((size_t)b * 1024 + n) * 6;
    #pragma unroll
    for (int t2 = 0; t2 < 6; t2++) {
        float va, vb; unpk(v2[t2], va, vb);
        float xa, xb; unpk(xp2[t2], xa, xb);
        va = fmaxf(va, 0.f); vb = fmaxf(vb, 0.f);
        Vs[p][c][2 * t2]     = fmaxf(xa * rw + rb + va, 0.f);
        Vs[p][c][2 * t2 + 1] = fmaxf(xb * rw + rb + vb, 0.f);
    }
    __syncthreads();

    if (tid < 96) {
        int p2 = tid / 12, t2 = tid % 12;
        float s = 0.f, s2 = 0.f;
        #pragma unroll
        for (int cc = 0; cc < 32; cc++) { float v = Vs[p2][cc][t2]; s += v; s2 += v * v; }
        float mu = s * (1.f / 32.f);
        float var = s2 * (1.f / 32.f) - mu * mu;
        float rstd = rsqrtf(var + 1e-5f);
        float* op = out + (((size_t)b * 1024 + n0 + p2) * 32) * 12 + t2;
        #pragma unroll
        for (int cc = 0; cc < 32; cc++)
            op[cc * 12] = (Vs[p2][cc][t2] - mu) * rstd * gf[cc] + bfin[cc];
    }
}

// ---------------- launch ----------------
extern "C" void kernel_launch(void* const* d_in, const int* in_sizes, int n_in,
                              void* d_out, int out_size) {
    const float* x     = (const float*)d_in[0];
    const float* resa  = (const float*)d_in[1];
    const float* peT   = (const float*)d_in[2];
    const float* gT    = (const float*)d_in[3];
    const float* bT    = (const float*)d_in[4];
    const float* WQt   = (const float*)d_in[5];
    const float* WKt   = (const float*)d_in[6];
    const float* WVt   = (const float*)d_in[7];
    const float* fct   = (const float*)d_in[8];
    const float* pcw   = (const float*)d_in[9];
    const float* pcb   = (const float*)d_in[10];
    const float* peS   = (const float*)d_in[11];
    const float* gS    = (const float*)d_in[12];
    const float* bS    = (const float*)d_in[13];
    const float* WQs   = (const float*)d_in[14];
    const float* WKs   = (const float*)d_in[15];
    const float* cheb  = (const float*)d_in[16];
    const float* adj   = (const float*)d_in[17];
    const float* cmask = (const float*)d_in[18];
    const float* Theta = (const float*)d_in[19];
    const float* w3    = (const float*)d_in[20];
    const float* b3    = (const float*)d_in[21];
    const float* w5    = (const float*)d_in[22];
    const float* b5    = (const float*)d_in[23];
    const float* w7    = (const float*)d_in[24];
    const float* b7    = (const float*)d_in[25];
    const float* rcw   = (const float*)d_in[26];
    const float* rcb   = (const float*)d_in[27];
    const float* fcw   = (const float*)d_in[28];
    const float* fcb   = (const float*)d_in[29];
    const float* gf    = (const float*)d_in[30];
    const float* bf    = (const float*)d_in[31];

    float* out  = (float*)d_out;
    float* reat = out + (size_t)16 * 1024 * 32 * 12;  // re_At after main output

    k_temporal_ln<<<192, 256>>>(x, peT, gT, bT);
    k_qkv<<<dim3(16, 4), 288>>>(WQt, WKt, WVt);
    k_tattn<<<48, 384>>>(resa, reat);
    k_tatout<<<192, 512>>>(fct);
    k_prep<<<6204, 256>>>(adj, cmask, cheb, w3, w5, w7);
    k_semx<<<2048, 256>>>(pcw, pcb, peS, gS, bS);
    k_qks_gemm<<<256, 256>>>(WQs, WKs);
    k_spatial<<<dim3(32, 3, 32), 256>>>(x);
    k_smerge<<<192, 256>>>();
    k_gtu<<<dim3(128, 16), 256>>>(x, Theta, b3, b5, b7, rcw, rcb, fcw, fcb, gf, bf, out);
}

// round 7
// speedup vs baseline: 1.6075x; 1.1357x over previous
#include <cuda_runtime.h>
#include <cuda_bf16.h>
#include <math.h>

// ---------------- constants ----------------
// B=16, N=1024, T=12, F=1, D_MODEL=512, D_K=D_V=32, H=3, K=3, C=32

// ---------------- scratch (static device memory; no allocation) ----------------
__device__ float g_TEmx[16 * 12 * 1024];      // (B,T,N)
__device__ float g_qkvp[4 * 16 * 12 * 288];   // partial QKV per n-quarter
__device__ float g_ctx [16 * 12 * 96];        // (B,T,96)
__device__ float g_TAT [16 * 12 * 1024];      // (B,T,N)
__device__ float g_SEmx[16 * 1024 * 512];     // (B,N,512)
__device__ float g_QKs [16 * 1024 * 192];     // (B,N,192): 0..95 = Qs, 96..191 = Ks
__device__ float g_rhs [16 * 3 * 1024 * 12];  // (B,K,N,T)
__device__ unsigned long long g_Wr2[32 * 15 * 32];    // {wa,wb} per (ci,pos,c)
__device__ unsigned long long g_bc [3 * 1024 * 1024]; // {adj*cmask, cheb} per (k,m,j)
__device__ unsigned long long g_part[4 * 7 * 49152];  // spatial partials [quarter][slot][jidx]

// ---------------- f32x2 helpers ----------------
__device__ __forceinline__ unsigned long long pk2(float a, float b) {
    unsigned long long r; asm("mov.b64 %0, {%1,%2};" : "=l"(r) : "f"(a), "f"(b)); return r;
}
__device__ __forceinline__ void unpk(unsigned long long v, float& a, float& b) {
    asm("mov.b64 {%0,%1}, %2;" : "=f"(a), "=f"(b) : "l"(v));
}
__device__ __forceinline__ unsigned long long ffma2(unsigned long long a, unsigned long long b, unsigned long long c) {
    unsigned long long d; asm("fma.rn.f32x2 %0, %1, %2, %3;" : "=l"(d) : "l"(a), "l"(b), "l"(c)); return d;
}
__device__ __forceinline__ unsigned long long mul2(unsigned long long a, unsigned long long b) {
    unsigned long long d; asm("mul.rn.f32x2 %0, %1, %2;" : "=l"(d) : "l"(a), "l"(b)); return d;
}
__device__ __forceinline__ unsigned long long add2(unsigned long long a, unsigned long long b) {
    unsigned long long d; asm("add.rn.f32x2 %0, %1, %2;" : "=l"(d) : "l"(a), "l"(b)); return d;
}

// ---------------- helpers ----------------
__device__ __forceinline__ void block_reduce2(float& s, float& s2, float* shm) {
    #pragma unroll
    for (int o = 16; o > 0; o >>= 1) {
        s  += __shfl_down_sync(0xFFFFFFFFu, s,  o);
        s2 += __shfl_down_sync(0xFFFFFFFFu, s2, o);
    }
    int nw = blockDim.x >> 5;
    int w = threadIdx.x >> 5, l = threadIdx.x & 31;
    if (l == 0) { shm[w] = s; shm[w + 32] = s2; }
    __syncthreads();
    if (w == 0) {
        s  = (l < nw) ? shm[l] : 0.f;
        s2 = (l < nw) ? shm[l + 32] : 0.f;
        #pragma unroll
        for (int o = 16; o > 0; o >>= 1) {
            s  += __shfl_down_sync(0xFFFFFFFFu, s,  o);
            s2 += __shfl_down_sync(0xFFFFFFFFu, s2, o);
        }
        if (l == 0) { shm[0] = s; shm[1] = s2; }
    }
    __syncthreads();
    s = shm[0]; s2 = shm[1];
}

// ---------------- K1: temporal embed + LN over N ----------------
__global__ void k_temporal_ln(const float* __restrict__ x, const float* __restrict__ peT,
                              const float* __restrict__ gT, const float* __restrict__ bT) {
    int b = blockIdx.x / 12, t = blockIdx.x % 12;
    int tid = threadIdx.x;
    __shared__ float shm[64];
    float vals[4]; float s = 0.f, s2 = 0.f;
    #pragma unroll
    for (int i = 0; i < 4; i++) {
        int n = tid + 256 * i;
        float v = x[((size_t)b * 1024 + n) * 12 + t] + peT[t * 1024 + n];
        vals[i] = v; s += v; s2 += v * v;
    }
    block_reduce2(s, s2, shm);
    float mu = s * (1.f / 1024.f);
    float rstd = rsqrtf(s2 * (1.f / 1024.f) - mu * mu + 1e-5f);
    float* op = g_TEmx + ((size_t)b * 12 + t) * 1024;
    #pragma unroll
    for (int i = 0; i < 4; i++) {
        int n = tid + 256 * i;
        op[n] = (vals[i] - mu) * rstd * gT[n] + bT[n];
    }
}

// ---------------- K2a: QKV projection partials; grid (16 b, 4 quarters), 288 thr ----------------
__global__ void k_qkv(const float* __restrict__ WQ, const float* __restrict__ WK,
                      const float* __restrict__ WV) {
    int b = blockIdx.x; int q = blockIdx.y;
    int tid = threadIdx.x;
    int n0 = q * 256;
    __shared__ unsigned long long Ep[6][256];   // pairs (2tp, 2tp+1)
    for (int i = tid; i < 1536; i += 288) {
        int tp = i >> 8; int nn = i & 255;
        float a = g_TEmx[((size_t)b * 12 + 2 * tp) * 1024 + n0 + nn];
        float c = g_TEmx[((size_t)b * 12 + 2 * tp + 1) * 1024 + n0 + nn];
        Ep[tp][nn] = pk2(a, c);
    }
    __syncthreads();
    const float* W; int cw;
    if (tid < 96)       { W = WQ; cw = tid; }
    else if (tid < 192) { W = WK; cw = tid - 96; }
    else                { W = WV; cw = tid - 192; }
    unsigned long long acc[6];
    #pragma unroll
    for (int i = 0; i < 6; i++) acc[i] = 0ull;
    #pragma unroll 4
    for (int nn = 0; nn < 256; nn++) {
        float wv = W[(n0 + nn) * 96 + cw];
        unsigned long long wp = pk2(wv, wv);
        #pragma unroll
        for (int tp = 0; tp < 6; tp++) acc[tp] = ffma2(Ep[tp][nn], wp, acc[tp]);
    }
    int qb = q * 55296 + b * 12 * 288;
    #pragma unroll
    for (int tp = 0; tp < 6; tp++) {
        float lo, hi; unpk(acc[tp], lo, hi);
        g_qkvp[qb + (2 * tp) * 288 + tid]     = lo;
        g_qkvp[qb + (2 * tp + 1) * 288 + tid] = hi;
    }
}

// ---------------- K2b: temporal attention per (b,h); sums quarter-partials; writes re_At ----------------
__global__ void k_tattn(const float* __restrict__ resa, float* __restrict__ reat) {
    int b = blockIdx.x / 3, h = blockIdx.x % 3;
    int tid = threadIdx.x;
    int t = tid >> 5, d = tid & 31;   // 384 threads = 12 warps x 32
    __shared__ float Q[12][32], Kt[12][32], V[12][32], S[12][12];

    int off = b * 3456 + t * 288 + h * 32 + d;
    Q [t][d] = g_qkvp[off]       + g_qkvp[off + 55296]       + g_qkvp[off + 110592]       + g_qkvp[off + 165888];
    Kt[t][d] = g_qkvp[off + 96]  + g_qkvp[off + 96 + 55296]  + g_qkvp[off + 96 + 110592]  + g_qkvp[off + 96 + 165888];
    V [t][d] = g_qkvp[off + 192] + g_qkvp[off + 192 + 55296] + g_qkvp[off + 192 + 110592] + g_qkvp[off + 192 + 165888];
    __syncthreads();

    if (tid < 144) {
        int qi = tid / 12, ki = tid % 12;
        float s = 0.f;
        #pragma unroll
        for (int dd = 0; dd < 32; dd++) s += Q[qi][dd] * Kt[ki][dd];
        s = s * 0.17677669529663687f + resa[((size_t)(b * 3 + h) * 12 + qi) * 12 + ki];
        S[qi][ki] = s;
        reat[((size_t)(b * 3 + h) * 12 + qi) * 12 + ki] = s;
    }
    __syncthreads();
    if (tid < 12) {
        float mxv = -1e30f;
        for (int kx = 0; kx < 12; kx++) mxv = fmaxf(mxv, S[tid][kx]);
        float smv = 0.f;
        for (int kx = 0; kx < 12; kx++) { float pv = __expf(S[tid][kx] - mxv); S[tid][kx] = pv; smv += pv; }
        float inv = 1.f / smv;
        for (int kx = 0; kx < 12; kx++) S[tid][kx] *= inv;
    }
    __syncthreads();
    float cv = 0.f;
    #pragma unroll
    for (int kx = 0; kx < 12; kx++) cv += S[t][kx] * V[kx][d];
    g_ctx[((size_t)b * 12 + t) * 96 + h * 32 + d] = cv;
}

// ---------------- K2c: TATout = LN(ctx @ fc_t + TEmx); 512 threads ----------------
__global__ void k_tatout(const float* __restrict__ fct) {
    int b = blockIdx.x / 12, t = blockIdx.x % 12;
    int tid = threadIdx.x;   // 512, one f32x2 col each
    __shared__ unsigned long long csp[96];
    __shared__ float shm[64];
    if (tid < 96) { float cv = g_ctx[((size_t)b * 12 + t) * 96 + tid]; csp[tid] = pk2(cv, cv); }
    __syncthreads();
    const unsigned long long* Eb2 = (const unsigned long long*)g_TEmx + ((size_t)b * 12 + t) * 512;
    const unsigned long long* fct2 = (const unsigned long long*)fct;
    unsigned long long v = Eb2[tid], u = 0ull;
    #pragma unroll 4
    for (int jx = 0; jx < 96; jx += 2) {
        v = ffma2(csp[jx],     fct2[(size_t)jx * 512 + tid],       v);
        u = ffma2(csp[jx + 1], fct2[(size_t)(jx + 1) * 512 + tid], u);
    }
    v = add2(v, u);
    float a, bv; unpk(v, a, bv);
    float s = a + bv, s2 = a * a + bv * bv;
    block_reduce2(s, s2, shm);
    float mu = s * (1.f / 1024.f);
    float rstd = rsqrtf(s2 * (1.f / 1024.f) - mu * mu + 1e-5f);
    unsigned long long* Tb2 = (unsigned long long*)g_TAT + ((size_t)b * 12 + t) * 512;
    Tb2[tid] = pk2((a - mu) * rstd, (bv - mu) * rstd);
}

// ---------------- K3a: pre_conv + pos_embed_S + LN over 512 -> SEmx (coalesced pcw staging) ----------------
__global__ void __launch_bounds__(256) k_semx(
        const float* __restrict__ pcw, const float* __restrict__ pcb,
        const float* __restrict__ peS, const float* __restrict__ gS,
        const float* __restrict__ bS) {
    int tid = threadIdx.x;
    int b = blockIdx.x >> 7;
    int n = ((blockIdx.x & 127) << 3) + (tid >> 5);
    int lane = tid & 31;
    // pw[t][d] = pcw[d*12 + t], staged with coalesced float4 loads
    __shared__ __align__(8) float pw[12][512];
    #pragma unroll
    for (int k = 0; k < 6; k++) {
        float4 v4 = *(const float4*)&pcw[tid * 24 + k * 4];
        float vv[4] = {v4.x, v4.y, v4.z, v4.w};
        #pragma unroll
        for (int e = 0; e < 4; e++) {
            int j = k * 4 + e;                // 0..23
            pw[j % 12][2 * tid + j / 12] = vv[e];
        }
    }
    __syncthreads();

    float tv = 0.f;
    if (lane < 12) tv = g_TAT[((size_t)b * 12 + lane) * 1024 + n];
    unsigned long long ttp[12];
    #pragma unroll
    for (int t = 0; t < 12; t++) {
        float sv = __shfl_sync(0xFFFFFFFFu, tv, t);
        ttp[t] = pk2(sv, sv);
    }
    const unsigned long long* pcb2 = (const unsigned long long*)pcb;
    const unsigned long long* peS2 = (const unsigned long long*)peS + (size_t)n * 256;
    unsigned long long v2[8];
    float s = 0.f, s2 = 0.f;
    #pragma unroll
    for (int i = 0; i < 8; i++) {
        int dp = lane + 32 * i;
        unsigned long long v = add2(pcb2[dp], peS2[dp]);
        #pragma unroll
        for (int t = 0; t < 12; t++)
            v = ffma2(ttp[t], *(const unsigned long long*)&pw[t][2 * dp], v);
        v2[i] = v;
        float a, bb; unpk(v, a, bb);
        s += a + bb; s2 += a * a + bb * bb;
    }
    #pragma unroll
    for (int o = 16; o > 0; o >>= 1) {
        s  += __shfl_xor_sync(0xFFFFFFFFu, s,  o);
        s2 += __shfl_xor_sync(0xFFFFFFFFu, s2, o);
    }
    float mu = s * (1.f / 512.f);
    float rstd = rsqrtf(s2 * (1.f / 512.f) - mu * mu + 1e-5f);
    const unsigned long long* g2  = (const unsigned long long*)gS;
    const unsigned long long* bb2 = (const unsigned long long*)bS;
    unsigned long long* o2 = (unsigned long long*)g_SEmx + ((size_t)b * 1024 + n) * 256;
    #pragma unroll
    for (int i = 0; i < 8; i++) {
        int dp = lane + 32 * i;
        float a, bbv; unpk(v2[i], a, bbv);
        float ga, gb; unpk(g2[dp], ga, gb);
        float ba, bx; unpk(bb2[dp], ba, bx);
        o2[dp] = pk2((a - mu) * rstd * ga + ba, (bbv - mu) * rstd * gb + bx);
    }
}

// ---------------- K3b: GEMM QKs = SEmx(16384x512) @ [WQ_s|WK_s](512x192), BM=64 ----------------
__global__ void __launch_bounds__(256) k_qks_gemm(const float* __restrict__ WQ,
                                                  const float* __restrict__ WK) {
    __shared__ __align__(16) float As[16][64];
    __shared__ __align__(16) float Bs[16][192];
    int m0 = blockIdx.x * 64;
    int tid = threadIdx.x;
    int tx = tid % 16, ty = tid / 16;
    unsigned long long acc2[4][6];
    #pragma unroll
    for (int r = 0; r < 4; r++)
        #pragma unroll
        for (int cq = 0; cq < 6; cq++) acc2[r][cq] = 0ull;

    for (int k0 = 0; k0 < 512; k0 += 16) {
        {
            int m = tid >> 2; int kq = (tid & 3) * 4;
            float4 a = *(const float4*)&g_SEmx[((size_t)m0 + m) * 512 + k0 + kq];
            As[kq + 0][m] = a.x; As[kq + 1][m] = a.y; As[kq + 2][m] = a.z; As[kq + 3][m] = a.w;
        }
        #pragma unroll
        for (int i = 0; i < 12; i++) {
            int e = tid + 256 * i; int kk = e / 192; int jl = e % 192;
            Bs[kk][jl] = (jl < 96) ? WQ[(k0 + kk) * 96 + jl] : WK[(k0 + kk) * 96 + (jl - 96)];
        }
        __syncthreads();
        #pragma unroll
        for (int kk = 0; kk < 16; kk++) {
            float4 a0 = *(const float4*)&As[kk][ty * 4];
            ulonglong2 b01 = *(const ulonglong2*)&Bs[kk][tx * 12];
            ulonglong2 b23 = *(const ulonglong2*)&Bs[kk][tx * 12 + 4];
            ulonglong2 b45 = *(const ulonglong2*)&Bs[kk][tx * 12 + 8];
            unsigned long long bv[6] = {b01.x, b01.y, b23.x, b23.y, b45.x, b45.y};
            float av[4] = {a0.x, a0.y, a0.z, a0.w};
            #pragma unroll
            for (int r = 0; r < 4; r++) {
                unsigned long long ap = pk2(av[r], av[r]);
                #pragma unroll
                for (int cq = 0; cq < 6; cq++) acc2[r][cq] = ffma2(ap, bv[cq], acc2[r][cq]);
            }
        }
        __syncthreads();
    }
    #pragma unroll
    for (int r = 0; r < 4; r++) {
        unsigned long long* base = (unsigned long long*)g_QKs + ((size_t)m0 + ty * 4 + r) * 96 + tx * 6;
        *(ulonglong2*)(base)     = make_ulonglong2(acc2[r][0], acc2[r][1]);
        *(ulonglong2*)(base + 2) = make_ulonglong2(acc2[r][2], acc2[r][3]);
        *(ulonglong2*)(base + 4) = make_ulonglong2(acc2[r][4], acc2[r][5]);
    }
}

// ---------------- K3c: prep = {adj*cmask, cheb} pack  +  gtu weight reorder ----------------
__global__ void k_prep(const float* __restrict__ adj, const float* __restrict__ cmask,
                       const float* __restrict__ cheb,
                       const float* __restrict__ w3, const float* __restrict__ w5,
                       const float* __restrict__ w7) {
    if (blockIdx.x < 6144) {
        int idx2 = blockIdx.x * 256 + threadIdx.x;   // 1.5M threads, 2 elems each
        int idx = idx2 * 2;
        int mj = idx & 1048575;
        float2 av = *(const float2*)&adj[mj];
        float2 cm = *(const float2*)&cmask[idx];
        float2 cb = *(const float2*)&cheb[idx];
        ulonglong2 o;
        o.x = pk2(av.x * cm.x, cb.x);
        o.y = pk2(av.y * cm.y, cb.y);
        *(ulonglong2*)&g_bc[idx] = o;
    } else {
        int idx = (blockIdx.x - 6144) * 256 + threadIdx.x;
        if (idx >= 15360) return;
        int c = idx & 31; int rest = idx >> 5; int pos = rest % 15; int ci = rest / 15;
        float wa, wb;
        if (pos < 3)      { wa = w3[(c * 32 + ci) * 3 + pos];       wb = w3[((c + 32) * 32 + ci) * 3 + pos]; }
        else if (pos < 8) { wa = w5[(c * 32 + ci) * 5 + (pos - 3)]; wb = w5[((c + 32) * 32 + ci) * 5 + (pos - 3)]; }
        else              { wa = w7[(c * 32 + ci) * 7 + (pos - 8)]; wb = w7[((c + 32) * 32 + ci) * 7 + (pos - 8)]; }
        g_Wr2[(ci * 15 + pos) * 32 + c] = pk2(wa, wb);
    }
}

// ---------------- K4: spatial column-softmax attention (m-split x4, bc reg-prefetch) ----------------
__global__ void __launch_bounds__(256, 2) k_spatial(const float* __restrict__ x) {
    int j0 = blockIdx.x * 32; int kk = blockIdx.y;
    int b = blockIdx.z >> 2; int quarter = blockIdx.z & 3;
    int tid = threadIdx.x; int lane = tid & 31; int g = tid >> 5;
    int j = j0 + lane;

    const unsigned long long* qk64 = (const unsigned long long*)g_QKs;

    unsigned long long kp[16];
    {
        const ulonglong2* kb = (const ulonglong2*)(qk64 + ((size_t)b * 1024 + j) * 96 + 48 + kk * 16);
        #pragma unroll
        for (int i = 0; i < 8; i++) { ulonglong2 v = kb[i]; kp[2 * i] = v.x; kp[2 * i + 1] = v.y; }
    }

    float sm = 0.f;
    unsigned long long acc[6];
    #pragma unroll
    for (int i = 0; i < 6; i++) acc[i] = 0ull;

    __shared__ __align__(16) unsigned long long Qs64[2][32][16];
    __shared__ unsigned long long xs64[2][32][6];

    const size_t kbase = (size_t)kk << 20;
    const size_t brow = (size_t)b * 1024;
    const int mbase = quarter * 256;

    // preload tile 0
    {
        #pragma unroll
        for (int i = 0; i < 2; i++) {
            int e = tid + 256 * i; int m = e >> 4; int d8 = e & 15;
            Qs64[0][m][d8] = qk64[(brow + mbase + m) * 96 + kk * 16 + d8];
        }
        if (tid < 192) {
            int m = tid / 6, i2 = tid % 6;
            xs64[0][m][i2] = ((const unsigned long long*)x)[(brow + mbase + m) * 6 + i2];
        }
    }
    // preload bc for it=0
    unsigned long long bcur[4];
    #pragma unroll
    for (int mi = 0; mi < 4; mi++)
        bcur[mi] = g_bc[kbase + (size_t)(mbase + g * 4 + mi) * 1024 + j];
    __syncthreads();

    for (int it = 0; it < 8; it++) {
        int cur = it & 1;
        unsigned long long pf0 = 0, pf1 = 0, pfx = 0, bnxt[4];
        if (it < 7) {
            int m0n = mbase + (it + 1) * 32;
            {
                int e = tid; int m = e >> 4; int d8 = e & 15;
                pf0 = qk64[(brow + m0n + m) * 96 + kk * 16 + d8];
            }
            {
                int e = tid + 256; int m = e >> 4; int d8 = e & 15;
                pf1 = qk64[(brow + m0n + m) * 96 + kk * 16 + d8];
            }
            if (tid < 192) {
                int m = tid / 6, i2 = tid % 6;
                pfx = ((const unsigned long long*)x)[(brow + m0n + m) * 6 + i2];
            }
            #pragma unroll
            for (int mi = 0; mi < 4; mi++)
                bnxt[mi] = g_bc[kbase + (size_t)(m0n + g * 4 + mi) * 1024 + j];
        }

        #pragma unroll
        for (int mi = 0; mi < 4; mi++) {
            int m = g * 4 + mi;
            unsigned long long s2 = 0ull;
            const ulonglong2* qrow = (const ulonglong2*)Qs64[cur][m];
            #pragma unroll
            for (int i = 0; i < 8; i++) {
                ulonglong2 q2 = qrow[i];
                s2 = ffma2(q2.x, kp[2 * i], s2);
                s2 = ffma2(q2.y, kp[2 * i + 1], s2);
            }
            float slo, shi; unpk(s2, slo, shi);
            float bias, cp; unpk(bcur[mi], bias, cp);
            float s = (slo + shi) * 0.17677669529663687f + bias;
            float p = __expf(s);
            sm += p;
            float w = p * cp;
            unsigned long long wp = pk2(w, w);
            #pragma unroll
            for (int i = 0; i < 6; i++) acc[i] = ffma2(wp, xs64[cur][m][i], acc[i]);
        }

        if (it < 7) {
            int nxt = cur ^ 1;
            { int e = tid;       Qs64[nxt][e >> 4][e & 15] = pf0; }
            { int e = tid + 256; Qs64[nxt][e >> 4][e & 15] = pf1; }
            if (tid < 192) xs64[nxt][tid / 6][tid % 6] = pfx;
            #pragma unroll
            for (int mi = 0; mi < 4; mi++) bcur[mi] = bnxt[mi];
        }
        __syncthreads();
    }

    // merge 8 warp-partials per j; write unnormalized partials for this quarter
    __shared__ float r_sm[8][32];
    __shared__ unsigned long long r_acc[8][32][6];
    r_sm[g][lane] = sm;
    #pragma unroll
    for (int i = 0; i < 6; i++) r_acc[g][lane][i] = acc[i];
    __syncthreads();
    if (g == 0) {
        float S = 0.f;
        unsigned long long o[6];
        #pragma unroll
        for (int i = 0; i < 6; i++) o[i] = 0ull;
        #pragma unroll
        for (int q = 0; q < 8; q++) {
            S += r_sm[q][lane];
            #pragma unroll
            for (int i = 0; i < 6; i++) o[i] = add2(o[i], r_acc[q][lane][i]);
        }
        int jidx = ((b * 3 + kk) << 10) + j;
        unsigned long long* pp = g_part + (size_t)quarter * 7 * 49152;
        #pragma unroll
        for (int i = 0; i < 6; i++) pp[i * 49152 + jidx] = o[i];
        pp[6 * 49152 + jidx] = pk2(S, S);
    }
}

// ---------------- K4b: merge the four m-quarters, normalize ----------------
__global__ void k_smerge() {
    int jidx = blockIdx.x * 256 + threadIdx.x;   // 49152
    unsigned long long o[6];
    float S = 0.f;
    #pragma unroll
    for (int i = 0; i < 6; i++) o[i] = 0ull;
    #pragma unroll
    for (int q = 0; q < 4; q++) {
        const unsigned long long* pp = g_part + (size_t)q * 7 * 49152;
        float sl, sh; unpk(pp[6 * 49152 + jidx], sl, sh);
        S += sl;
        #pragma unroll
        for (int i = 0; i < 6; i++) o[i] = add2(o[i], pp[i * 49152 + jidx]);
    }
    float inv = 1.f / S;
    unsigned long long ip = pk2(inv, inv);
    unsigned long long* rp = (unsigned long long*)g_rhs + (size_t)jidx * 6;
    #pragma unroll
    for (int i = 0; i < 6; i++) rp[i] = mul2(o[i], ip);
}

// ---------------- K6: Theta contraction + GTUs + fcmy + residual + final LN (2-pass) ----------------
__global__ void __launch_bounds__(256, 2) k_gtu(
    const float* __restrict__ x, const float* __restrict__ Theta,
    const float* __restrict__ b3, const float* __restrict__ b5, const float* __restrict__ b7,
    const float* __restrict__ rcw, const float* __restrict__ rcb,
    const float* __restrict__ fcw, const float* __restrict__ fcb,
    const float* __restrict__ gf, const float* __restrict__ bfin,
    float* __restrict__ out) {
    int n0 = blockIdx.x * 8; int b = blockIdx.y;
    int tid = threadIdx.x; int c = tid & 31; int p = tid >> 5; int n = n0 + p;
    __shared__ unsigned long long Xp[8][32][12];
    __shared__ float Vs[8][32][12];
    __shared__ unsigned long long fcw2[24][6];

    if (tid < 144) {
        int w = tid / 6, t2 = tid % 6;
        fcw2[w][t2] = pk2(fcw[w * 12 + 2 * t2], fcw[w * 12 + 2 * t2 + 1]);
    }

    {
        float th0 = Theta[c], th1 = Theta[32 + c], th2 = Theta[64 + c];
        const float* r0 = g_rhs + (((size_t)b * 3 + 0) * 1024 + n) * 12;
        const float* r1 = g_rhs + (((size_t)b * 3 + 1) * 1024 + n) * 12;
        const float* r2 = g_rhs + (((size_t)b * 3 + 2) * 1024 + n) * 12;
        #pragma unroll
        for (int t = 0; t < 12; t++) {
            float v = r0[t] * th0 + r1[t] * th1 + r2[t] * th2;
            v = fmaxf(v, 0.f);
            Xp[p][c][t] = pk2(v, v);
        }
    }
    __syncthreads();

    // v2 accumulates fcmy across both passes
    unsigned long long v2[6];
    {
        const unsigned long long* fcb2 = (const unsigned long long*)fcb;
        #pragma unroll
        for (int t2 = 0; t2 < 6; t2++) v2[t2] = fcb2[t2];
    }

    // ---- pass 1: gtu3 (w 0..9) + gtu7 (w 18..23), 16 accumulators ----
    {
        unsigned long long yA[16];
        unsigned long long i3 = pk2(b3[c], b3[c + 32]);
        unsigned long long i7 = pk2(b7[c], b7[c + 32]);
        #pragma unroll
        for (int w = 0; w < 10; w++) yA[w] = i3;
        #pragma unroll
        for (int w = 0; w < 6; w++)  yA[10 + w] = i7;

        for (int ci = 0; ci < 32; ci++) {
            unsigned long long Xr[12];
            #pragma unroll
            for (int t = 0; t < 12; t++) Xr[t] = Xp[p][ci][t];
            const unsigned long long* wr = g_Wr2 + (size_t)ci * 15 * 32 + c;
            #pragma unroll
            for (int dt = 0; dt < 3; dt++) {
                unsigned long long wv = __ldg(&wr[dt * 32]);
                #pragma unroll
                for (int w = 0; w < 10; w++) yA[w] = ffma2(Xr[w + dt], wv, yA[w]);
            }
            #pragma unroll
            for (int dt = 0; dt < 7; dt++) {
                unsigned long long wv = __ldg(&wr[(8 + dt) * 32]);
                #pragma unroll
                for (int w = 0; w < 6; w++) yA[10 + w] = ffma2(Xr[w + dt], wv, yA[10 + w]);
            }
        }
        #pragma unroll
        for (int w = 0; w < 16; w++) {
            float ya, yb; unpk(yA[w], ya, yb);
            float tv = 1.f - 2.f / (__expf(2.f * ya) + 1.f);
            float sg = 1.f / (1.f + __expf(-yb));
            float gv = tv * sg;
            unsigned long long gp = pk2(gv, gv);
            int row = (w < 10) ? w : (8 + w);   // w 10..15 -> rows 18..23
            #pragma unroll
            for (int t2 = 0; t2 < 6; t2++) v2[t2] = ffma2(gp, fcw2[row][t2], v2[t2]);
        }
    }

    // ---- pass 2: gtu5 (w 10..17), 8 accumulators ----
    {
        unsigned long long yB[8];
        unsigned long long i5 = pk2(b5[c], b5[c + 32]);
        #pragma unroll
        for (int w = 0; w < 8; w++) yB[w] = i5;

        for (int ci = 0; ci < 32; ci++) {
            unsigned long long Xr[12];
            #pragma unroll
            for (int t = 0; t < 12; t++) Xr[t] = Xp[p][ci][t];
            const unsigned long long* wr = g_Wr2 + (size_t)ci * 15 * 32 + c;
            #pragma unroll
            for (int dt = 0; dt < 5; dt++) {
                unsigned long long wv = __ldg(&wr[(3 + dt) * 32]);
                #pragma unroll
                for (int w = 0; w < 8; w++) yB[w] = ffma2(Xr[w + dt], wv, yB[w]);
            }
        }
        #pragma unroll
        for (int w = 0; w < 8; w++) {
            float ya, yb; unpk(yB[w], ya, yb);
            float tv = 1.f - 2.f / (__expf(2.f * ya) + 1.f);
            float sg = 1.f / (1.f + __expf(-yb));
            float gv = tv * sg;
            unsigned long long gp = pk2(gv, gv);
            #pragma unroll
            for (int t2 = 0; t2 < 6; t2++) v2[t2] = ffma2(gp, fcw2[10 + w][t2], v2[t2]);
        }
    }

    float rw = rcw[c], rb = rcb[c];
    const unsigned long long* xp2 = (const unsigned long long*)x + ((size_t)b * 1024 + n) * 6;
    #pragma unroll
    for (int t2 = 0; t2 < 6; t2++) {
        float va, vb; unpk(v2[t2], va, vb);
        float xa, xb; unpk(xp2[t2], xa, xb);
        va = fmaxf(va, 0.f); vb = fmaxf(vb, 0.f);
        Vs[p][c][2 * t2]     = fmaxf(xa * rw + rb + va, 0.f);
        Vs[p][c][2 * t2 + 1] = fmaxf(xb * rw + rb + vb, 0.f);
    }
    __syncthreads();

    if (tid < 96) {
        int p2 = tid / 12, t2 = tid % 12;
        float s = 0.f, s2 = 0.f;
        #pragma unroll
        for (int cc = 0; cc < 32; cc++) { float v = Vs[p2][cc][t2]; s += v; s2 += v * v; }
        float mu = s * (1.f / 32.f);
        float var = s2 * (1.f / 32.f) - mu * mu;
        float rstd = rsqrtf(var + 1e-5f);
        float* op = out + (((size_t)b * 1024 + n0 + p2) * 32) * 12 + t2;
        #pragma unroll
        for (int cc = 0; cc < 32; cc++)
            op[cc * 12] = (Vs[p2][cc][t2] - mu) * rstd * gf[cc] + bfin[cc];
    }
}

// ---------------- launch ----------------
extern "C" void kernel_launch(void* const* d_in, const int* in_sizes, int n_in,
                              void* d_out, int out_size) {
    const float* x     = (const float*)d_in[0];
    const float* resa  = (const float*)d_in[1];
    const float* peT   = (const float*)d_in[2];
    const float* gT    = (const float*)d_in[3];
    const float* bT    = (const float*)d_in[4];
    const float* WQt   = (const float*)d_in[5];
    const float* WKt   = (const float*)d_in[6];
    const float* WVt   = (const float*)d_in[7];
    const float* fct   = (const float*)d_in[8];
    const float* pcw   = (const float*)d_in[9];
    const float* pcb   = (const float*)d_in[10];
    const float* peS   = (const float*)d_in[11];
    const float* gS    = (const float*)d_in[12];
    const float* bS    = (const float*)d_in[13];
    const float* WQs   = (const float*)d_in[14];
    const float* WKs   = (const float*)d_in[15];
    const float* cheb  = (const float*)d_in[16];
    const float* adj   = (const float*)d_in[17];
    const float* cmask = (const float*)d_in[18];
    const float* Theta = (const float*)d_in[19];
    const float* w3    = (const float*)d_in[20];
    const float* b3    = (const float*)d_in[21];
    const float* w5    = (const float*)d_in[22];
    const float* b5    = (const float*)d_in[23];
    const float* w7    = (const float*)d_in[24];
    const float* b7    = (const float*)d_in[25];
    const float* rcw   = (const float*)d_in[26];
    const float* rcb   = (const float*)d_in[27];
    const float* fcw   = (const float*)d_in[28];
    const float* fcb   = (const float*)d_in[29];
    const float* gf    = (const float*)d_in[30];
    const float* bf    = (const float*)d_in[31];

    float* out  = (float*)d_out;
    float* reat = out + (size_t)16 * 1024 * 32 * 12;  // re_At after main output

    k_temporal_ln<<<192, 256>>>(x, peT, gT, bT);
    k_qkv<<<dim3(16, 4), 288>>>(WQt, WKt, WVt);
    k_tattn<<<48, 384>>>(resa, reat);
    k_tatout<<<192, 512>>>(fct);
    k_prep<<<6204, 256>>>(adj, cmask, cheb, w3, w5, w7);
    k_semx<<<2048, 256>>>(pcw, pcb, peS, gS, bS);
    k_qks_gemm<<<256, 256>>>(WQs, WKs);
    k_spatial<<<dim3(32, 3, 64), 256>>>(x);
    k_smerge<<<192, 256>>>();
    k_gtu<<<dim3(128, 16), 256>>>(x, Theta, b3, b5, b7, rcw, rcb, fcw, fcb, gf, bf, out);
}